// round 5
// baseline (speedup 1.0000x reference)
#include <cuda_runtime.h>
#include <cuda_bf16.h>
#include <math.h>
#include <cstdint>

#define Bsz 2
#define Lsz 2048
#define Esz 1024
#define Hsz 16
#define Dsz 64
#define NROW 4096               // Bsz*Lsz
#define BLE  (Bsz*Lsz*Esz)      // 4,194,304
#define BHD  ((size_t)Bsz*Hsz*Lsz*Dsz)
#define KA   4096               // int8 A_cat width

// fp32 scratch: qr qi kr ki vr vi or oi
__device__ float g_scratch[8u * BLE];
// int8 A_cat (reused q,k,v,o)
__device__ int8_t g_acat[(size_t)NROW * KA];                  // 16 MB
// int8 weights: 4 layers x {BM1,BS1,BM2,BS2} each [1024][4096]
__device__ int8_t g_bq[16ull * Esz * KA];                     // 64 MB
// attention bf16 arrays: q(4) k(4) v(4)
__device__ __nv_bfloat16 g_attn[12ull * BHD];                 // 96 MB
// scales: [0..3]=W absmax (q,k,v,o), [4..7]=X absmax (q,k,v,o)
__device__ float g_scales[16];

// ---------------------------------------------------------------------------
// helpers
// ---------------------------------------------------------------------------
__device__ __forceinline__ uint32_t smem_u32(const void* p) {
    uint32_t a;
    asm("{ .reg .u64 t; cvta.to.shared.u64 t, %1; cvt.u32.u64 %0, t; }" : "=r"(a) : "l"(p));
    return a;
}
__device__ __forceinline__ void cpa16(uint32_t dst, const void* src) {
    asm volatile("cp.async.cg.shared.global [%0], [%1], 16;" :: "r"(dst), "l"(src));
}
#define CPA_COMMIT() asm volatile("cp.async.commit_group;" ::: "memory")
#define CPA_WAIT(n)  asm volatile("cp.async.wait_group %0;" :: "n"(n) : "memory")

__device__ __forceinline__ void ldsm_x4(uint32_t* r, uint32_t addr) {
    asm volatile("ldmatrix.sync.aligned.m8n8.x4.shared.b16 {%0,%1,%2,%3}, [%4];"
        : "=r"(r[0]), "=r"(r[1]), "=r"(r[2]), "=r"(r[3]) : "r"(addr));
}
__device__ __forceinline__ void ldsm_x4_t(uint32_t* r, uint32_t addr) {
    asm volatile("ldmatrix.sync.aligned.m8n8.x4.trans.shared.b16 {%0,%1,%2,%3}, [%4];"
        : "=r"(r[0]), "=r"(r[1]), "=r"(r[2]), "=r"(r[3]) : "r"(addr));
}
__device__ __forceinline__ void mma16816(float* c, const uint32_t* a, const uint32_t* b) {
    asm volatile("mma.sync.aligned.m16n8k16.row.col.f32.bf16.bf16.f32 "
        "{%0,%1,%2,%3}, {%4,%5,%6,%7}, {%8,%9}, {%0,%1,%2,%3};"
        : "+f"(c[0]), "+f"(c[1]), "+f"(c[2]), "+f"(c[3])
        : "r"(a[0]), "r"(a[1]), "r"(a[2]), "r"(a[3]), "r"(b[0]), "r"(b[1]));
}
__device__ __forceinline__ void imma16832(int* c, const uint32_t* a, const uint32_t* b) {
    asm volatile("mma.sync.aligned.m16n8k32.row.col.s32.s8.s8.s32 "
        "{%0,%1,%2,%3}, {%4,%5,%6,%7}, {%8,%9}, {%0,%1,%2,%3};"
        : "+r"(c[0]), "+r"(c[1]), "+r"(c[2]), "+r"(c[3])
        : "r"(a[0]), "r"(a[1]), "r"(a[2]), "r"(a[3]), "r"(b[0]), "r"(b[1]));
}
__device__ __forceinline__ float fexp2(float x) {
    float y;
    asm("ex2.approx.ftz.f32 %0, %1;" : "=f"(y) : "f"(x));
    return y;
}
__device__ __forceinline__ void split1(float x, __nv_bfloat16& h, __nv_bfloat16& l) {
    h = __float2bfloat16(x);
    l = __float2bfloat16(x - __bfloat162float(h));
}
__device__ __forceinline__ uint32_t packbf2(__nv_bfloat16 a, __nv_bfloat16 b) {
    __nv_bfloat162 t; t.x = a; t.y = b;
    return *(uint32_t*)&t;
}
__device__ __forceinline__ void store4(__nv_bfloat16* p, __nv_bfloat16 a, __nv_bfloat16 b,
                                       __nv_bfloat16 c, __nv_bfloat16 d) {
    uint2 w;
    w.x = packbf2(a, b); w.y = packbf2(c, d);
    *(uint2*)p = w;
}
// quantize v -> digits a,b with q = a*128 + b, |q| <= 16255
__device__ __forceinline__ void qdigits(float v, float inv, int8_t& a, int8_t& b) {
    int q = (int)lrintf(fminf(fmaxf(v * inv, -16255.f), 16255.f));
    int ai = ((q + 16448) >> 7) - 128;
    a = (int8_t)ai;
    b = (int8_t)(q - (ai << 7));
}

// ---------------------------------------------------------------------------
// scale kernels
// ---------------------------------------------------------------------------
__global__ void zero_scales_kernel() {
    if (threadIdx.x < 16) g_scales[threadIdx.x] = 0.f;
}

__global__ __launch_bounds__(256) void absmax_kernel(
    const float* __restrict__ x, const float* __restrict__ y, int n4, float* out)
{
    float m = 0.f;
    int idx = blockIdx.x * 256 + threadIdx.x;
    const int stride = gridDim.x * 256;
    for (int i = idx; i < n4; i += stride) {
        float4 a = ((const float4*)x)[i];
        float4 b = ((const float4*)y)[i];
        m = fmaxf(m, fmaxf(fmaxf(fabsf(a.x), fabsf(a.y)), fmaxf(fabsf(a.z), fabsf(a.w))));
        m = fmaxf(m, fmaxf(fmaxf(fabsf(b.x), fabsf(b.y)), fmaxf(fabsf(b.z), fabsf(b.w))));
    }
    #pragma unroll
    for (int s = 16; s > 0; s >>= 1)
        m = fmaxf(m, __shfl_xor_sync(0xffffffffu, m, s));
    if ((threadIdx.x & 31) == 0)
        atomicMax((unsigned int*)out, __float_as_uint(m));
}

// ---------------------------------------------------------------------------
// quantX: fp32 (xr, xi) -> A_cat int8 [M][4096]
// layout: part p (r=0,i=1) at cols p*2048; orig k in chunk (k>>7):
//   a-digits at p*2048 + (k>>7)*256 + (k&127); b-digits at +128
// ---------------------------------------------------------------------------
__global__ __launch_bounds__(256) void quantX_kernel(
    const float* __restrict__ xr, const float* __restrict__ xi,
    const float* __restrict__ sp, int8_t* __restrict__ A)
{
    const float inv = 16255.f / *sp;
    const int total = NROW * Esz / 4;
    int idx = blockIdx.x * 256 + threadIdx.x;
    const int stride = gridDim.x * 256;
    for (; idx < total; idx += stride) {
        const int m = idx >> 8;
        const int k4 = (idx & 255) << 2;
        float4 vr = ((const float4*)xr)[idx];
        float4 vi = ((const float4*)xi)[idx];
        int8_t ar[4], br_[4], ai[4], bi_[4];
        qdigits(vr.x, inv, ar[0], br_[0]); qdigits(vr.y, inv, ar[1], br_[1]);
        qdigits(vr.z, inv, ar[2], br_[2]); qdigits(vr.w, inv, ar[3], br_[3]);
        qdigits(vi.x, inv, ai[0], bi_[0]); qdigits(vi.y, inv, ai[1], bi_[1]);
        qdigits(vi.z, inv, ai[2], bi_[2]); qdigits(vi.w, inv, ai[3], bi_[3]);
        const int base = ((k4 >> 7) << 8) + (k4 & 127);
        int8_t* p = A + (size_t)m * KA + base;
        *(char4*)(p +    0) = make_char4(ar[0], ar[1], ar[2], ar[3]);
        *(char4*)(p +  128) = make_char4(br_[0], br_[1], br_[2], br_[3]);
        *(char4*)(p + 2048) = make_char4(ai[0], ai[1], ai[2], ai[3]);
        *(char4*)(p + 2176) = make_char4(bi_[0], bi_[1], bi_[2], bi_[3]);
    }
}

// ---------------------------------------------------------------------------
// quantW: fp32 (Wr, Wi) -> BM1/BS1/BM2/BS2 int8 [N][4096]
// BM1 = [aWr | aWr | -aWi | -aWi]  (per chunk pair: a-col, b-col same content)
// BS1 = [bWr | bWr | -bWi | -bWi]
// BM2 = [aWi | aWi |  aWr |  aWr]
// BS2 = [bWi | bWi |  bWr |  bWr]
// ---------------------------------------------------------------------------
__global__ __launch_bounds__(256) void quantW_kernel(
    const float* __restrict__ Wr, const float* __restrict__ Wi,
    const float* __restrict__ sp,
    int8_t* __restrict__ BM1, int8_t* __restrict__ BS1,
    int8_t* __restrict__ BM2, int8_t* __restrict__ BS2)
{
    const float inv = 16255.f / *sp;
    const int total = Esz * Esz / 4;
    int idx = blockIdx.x * 256 + threadIdx.x;
    const int stride = gridDim.x * 256;
    for (; idx < total; idx += stride) {
        const int n = idx >> 8;
        const int k4 = (idx & 255) << 2;
        float4 wr = ((const float4*)Wr)[idx];
        float4 wi = ((const float4*)Wi)[idx];
        int8_t aR[4], bR[4], aI[4], bI[4], nA[4], nB[4];
        qdigits(wr.x, inv, aR[0], bR[0]); qdigits(wr.y, inv, aR[1], bR[1]);
        qdigits(wr.z, inv, aR[2], bR[2]); qdigits(wr.w, inv, aR[3], bR[3]);
        qdigits(wi.x, inv, aI[0], bI[0]); qdigits(wi.y, inv, aI[1], bI[1]);
        qdigits(wi.z, inv, aI[2], bI[2]); qdigits(wi.w, inv, aI[3], bI[3]);
        qdigits(-wi.x, inv, nA[0], nB[0]); qdigits(-wi.y, inv, nA[1], nB[1]);
        qdigits(-wi.z, inv, nA[2], nB[2]); qdigits(-wi.w, inv, nA[3], nB[3]);
        const int base = ((k4 >> 7) << 8) + (k4 & 127);
        const size_t off = (size_t)n * KA + base;
        char4 caR = make_char4(aR[0], aR[1], aR[2], aR[3]);
        char4 cbR = make_char4(bR[0], bR[1], bR[2], bR[3]);
        char4 caI = make_char4(aI[0], aI[1], aI[2], aI[3]);
        char4 cbI = make_char4(bI[0], bI[1], bI[2], bI[3]);
        char4 cnA = make_char4(nA[0], nA[1], nA[2], nA[3]);
        char4 cnB = make_char4(nB[0], nB[1], nB[2], nB[3]);
        *(char4*)(BM1+off)      = caR; *(char4*)(BM1+off+128)  = caR;
        *(char4*)(BM1+off+2048) = cnA; *(char4*)(BM1+off+2176) = cnA;
        *(char4*)(BS1+off)      = cbR; *(char4*)(BS1+off+128)  = cbR;
        *(char4*)(BS1+off+2048) = cnB; *(char4*)(BS1+off+2176) = cnB;
        *(char4*)(BM2+off)      = caI; *(char4*)(BM2+off+128)  = caI;
        *(char4*)(BM2+off+2048) = caR; *(char4*)(BM2+off+2176) = caR;
        *(char4*)(BS2+off)      = cbI; *(char4*)(BS2+off+128)  = cbI;
        *(char4*)(BS2+off+2048) = cbR; *(char4*)(BS2+off+2176) = cbR;
    }
}

// ---------------------------------------------------------------------------
// attention prep: fp32 [B,L,H*D] -> 4 bf16 arrays [BH][L][D] (hi/lo, r/i)
// ---------------------------------------------------------------------------
__global__ __launch_bounds__(256) void attprep_kernel(
    const float* __restrict__ xr, const float* __restrict__ xi,
    __nv_bfloat16* __restrict__ rh, __nv_bfloat16* __restrict__ rl,
    __nv_bfloat16* __restrict__ ih, __nv_bfloat16* __restrict__ il)
{
    const int total = NROW * Esz / 4;
    int idx = blockIdx.x * 256 + threadIdx.x;
    const int stride = gridDim.x * 256;
    for (; idx < total; idx += stride) {
        const int m = idx >> 8;
        const int e = (idx & 255) << 2;
        const int b = m >> 11, l = m & 2047;
        const int h = e >> 6, d = e & 63;
        const size_t o = (((size_t)(b * Hsz + h) * Lsz) + l) * Dsz + d;
        float4 vr = ((const float4*)xr)[idx];
        float4 vi = ((const float4*)xi)[idx];
        __nv_bfloat16 a[4], c[4], p[4], q[4];
        split1(vr.x, a[0], c[0]); split1(vr.y, a[1], c[1]);
        split1(vr.z, a[2], c[2]); split1(vr.w, a[3], c[3]);
        split1(vi.x, p[0], q[0]); split1(vi.y, p[1], q[1]);
        split1(vi.z, p[2], q[2]); split1(vi.w, p[3], q[3]);
        store4(rh + o, a[0], a[1], a[2], a[3]);
        store4(rl + o, c[0], c[1], c[2], c[3]);
        store4(ih + o, p[0], p[1], p[2], p[3]);
        store4(il + o, q[0], q[1], q[2], q[3]);
    }
}

// ---------------------------------------------------------------------------
// int8 complex GEMM. CTA 64x64, 8 warps (2m x 4n), warp 32x16.
// chunk = 256 int8 per row (a-half 128B, b-half 128B).
// accumulator sets: 0=hi1 1=mid1 2=lo1 (Yr), 3=hi2 4=mid2 5=lo2 (Yi)
// Yr = s*(hi1*16384 + mid1*128 + lo1) + br ; Yi likewise with sets 3..5.
// ---------------------------------------------------------------------------
#define IGM 64
#define IGN 64
#define INCHK 16
#define IASTR 272
#define IA_BYTES (64 * IASTR)             // 17408
#define IB_BYTES (64 * IASTR)
#define ISTAGE (IA_BYTES + 4 * IB_BYTES)  // 87040
#define IGEMM_SMEM (2 * ISTAGE)           // 174080

__global__ __launch_bounds__(256, 1) void igemm_kernel(
    const int8_t* __restrict__ A,
    const int8_t* __restrict__ BM1, const int8_t* __restrict__ BS1,
    const int8_t* __restrict__ BM2, const int8_t* __restrict__ BS2,
    const float* __restrict__ sxp, const float* __restrict__ swp,
    const float* __restrict__ br, const float* __restrict__ bi,
    float* __restrict__ Yr, float* __restrict__ Yi)
{
    extern __shared__ char smem[];
    const uint32_t sb = smem_u32(smem);
    const int tid = threadIdx.x;
    const int lane = tid & 31;
    const int wid = tid >> 5;
    const int wm = wid >> 2;            // 0..1  (32 m-rows each)
    const int wn = wid & 3;             // 0..3  (16 n-cols each)
    const int m0 = blockIdx.y * IGM;
    const int n0 = blockIdx.x * IGN;

    const int8_t* Bt[4] = {BM1, BS1, BM2, BS2};

    auto load_chunk = [&](int c, int buf) {
        const uint32_t s = sb + buf * ISTAGE;
        const int kc = c * 256;
        #pragma unroll
        for (int i = 0; i < 4; ++i) {
            const int op = tid + i * 256;
            const int r = op >> 4, q = op & 15;
            cpa16(s + r * IASTR + q * 16, A + (size_t)(m0 + r) * KA + kc + q * 16);
        }
        #pragma unroll
        for (int t = 0; t < 4; ++t) {
            #pragma unroll
            for (int i = 0; i < 4; ++i) {
                const int op = tid + i * 256;
                const int r = op >> 4, q = op & 15;
                cpa16(s + IA_BYTES + t * IB_BYTES + r * IASTR + q * 16,
                      Bt[t] + (size_t)(n0 + r) * KA + kc + q * 16);
            }
        }
        CPA_COMMIT();
    };

    int acc[6][2][2][4] = {};   // [set][mt][n8][frag]

    const uint32_t aRow = (uint32_t)(wm * 32 + (lane & 15));
    const uint32_t aCol = (uint32_t)((lane >> 4) * 16);
    const uint32_t bRow = (uint32_t)(wn * 16 + (lane & 7) + ((lane >> 4) << 3));
    const uint32_t bCol = (uint32_t)(((lane >> 3) & 1) * 16);

    load_chunk(0, 0);

    for (int c = 0; c < INCHK; ++c) {
        if (c + 1 < INCHK) {
            load_chunk(c + 1, (c + 1) & 1);
            CPA_WAIT(1);
        } else {
            CPA_WAIT(0);
        }
        __syncthreads();

        const uint32_t s = sb + (c & 1) * ISTAGE;
        const uint32_t aB = s + aRow * IASTR + aCol;
        const uint32_t bB = s + IA_BYTES + bRow * IASTR + bCol;

        #pragma unroll
        for (int ks = 0; ks < 8; ++ks) {
            const int par = ks >> 2;   // 0: a-digits, 1: b-digits (compile-time)
            uint32_t a0[4], a1[4];
            ldsm_x4(a0, aB + ks * 32);
            ldsm_x4(a1, aB + 16 * IASTR + ks * 32);
            #pragma unroll
            for (int t = 0; t < 4; ++t) {
                uint32_t bf[4];
                ldsm_x4(bf, bB + t * IB_BYTES + ks * 32);
                const int set = (t < 2) ? (t + par) : (t + 1 + par);
                imma16832(acc[set][0][0], a0, &bf[0]);
                imma16832(acc[set][0][1], a0, &bf[2]);
                imma16832(acc[set][1][0], a1, &bf[0]);
                imma16832(acc[set][1][1], a1, &bf[2]);
            }
        }
        __syncthreads();
    }

    const float sxw = (*sxp) * (*swp) * (1.0f / (16255.f * 16255.f));
    const int rowb = m0 + wm * 32 + (lane >> 2);
    const int colb = n0 + wn * 16 + (lane & 3) * 2;
    #pragma unroll
    for (int mt = 0; mt < 2; ++mt) {
        #pragma unroll
        for (int n8 = 0; n8 < 2; ++n8) {
            const int col = colb + n8 * 8;
            const int row = rowb + mt * 16;
            const float br0 = __ldg(&br[col]), br1 = __ldg(&br[col + 1]);
            const float bi0 = __ldg(&bi[col]), bi1 = __ldg(&bi[col + 1]);
            #pragma unroll
            for (int hf = 0; hf < 2; ++hf) {
                const int r = row + hf * 8;
                const int f = hf * 2;
                float2 v;
                v.x = sxw * ((float)acc[0][mt][n8][f]   * 16384.f
                           + (float)acc[1][mt][n8][f]   * 128.f
                           + (float)acc[2][mt][n8][f])  + br0;
                v.y = sxw * ((float)acc[0][mt][n8][f+1] * 16384.f
                           + (float)acc[1][mt][n8][f+1] * 128.f
                           + (float)acc[2][mt][n8][f+1]) + br1;
                *(float2*)&Yr[(size_t)r * Esz + col] = v;
                v.x = sxw * ((float)acc[3][mt][n8][f]   * 16384.f
                           + (float)acc[4][mt][n8][f]   * 128.f
                           + (float)acc[5][mt][n8][f])  + bi0;
                v.y = sxw * ((float)acc[3][mt][n8][f+1] * 16384.f
                           + (float)acc[4][mt][n8][f+1] * 128.f
                           + (float)acc[5][mt][n8][f+1]) + bi1;
                *(float2*)&Yi[(size_t)r * Esz + col] = v;
            }
        }
    }
}

// ---------------------------------------------------------------------------
// Tensor-core flash attention (bf16 hi/lo, unchanged from round 4 — passing)
// ---------------------------------------------------------------------------
#define AT_STR 144
#define AT_MAT (64 * AT_STR)
#define AT_QMAT (128 * AT_STR)
#define AT_QBYTES (4 * AT_QMAT)
#define AT_STAGE (8 * AT_MAT)
#define AT_SMEM (AT_QBYTES + 2 * AT_STAGE)
#define NKT (Lsz / 64)

__global__ __launch_bounds__(256, 1) void attn_tc_kernel(
    const __nv_bfloat16* __restrict__ QRH, const __nv_bfloat16* __restrict__ QRL,
    const __nv_bfloat16* __restrict__ QIH, const __nv_bfloat16* __restrict__ QIL,
    const __nv_bfloat16* __restrict__ KRH, const __nv_bfloat16* __restrict__ KRL,
    const __nv_bfloat16* __restrict__ KIH, const __nv_bfloat16* __restrict__ KIL,
    const __nv_bfloat16* __restrict__ VRH, const __nv_bfloat16* __restrict__ VRL,
    const __nv_bfloat16* __restrict__ VIH, const __nv_bfloat16* __restrict__ VIL,
    float* __restrict__ out_r, float* __restrict__ out_i)
{
    extern __shared__ char smem[];
    const uint32_t sb = smem_u32(smem);
    const int tid = threadIdx.x;
    const int lane = tid & 31;
    const int wid = tid >> 5;
    const int q0 = blockIdx.x * 128;
    const int bh = blockIdx.y;
    const size_t pb = (size_t)bh * Lsz * Dsz;

    const __nv_bfloat16* Qm[4] = {QRH + pb, QRL + pb, QIH + pb, QIL + pb};
    const __nv_bfloat16* Km[8] = {KRH + pb, KRL + pb, KIH + pb, KIL + pb,
                                  VRH + pb, VRL + pb, VIH + pb, VIL + pb};

    #pragma unroll
    for (int mat = 0; mat < 4; ++mat) {
        #pragma unroll
        for (int i = 0; i < 4; ++i) {
            const int op = tid + i * 256;
            const int r = op >> 3, q = op & 7;
            cpa16(sb + mat * AT_QMAT + r * AT_STR + q * 16,
                  Qm[mat] + (size_t)(q0 + r) * Dsz + q * 8);
        }
    }
    CPA_COMMIT();

    auto issue_kv = [&](int kt, int buf) {
        const uint32_t base = sb + AT_QBYTES + buf * AT_STAGE;
        #pragma unroll
        for (int mat = 0; mat < 8; ++mat) {
            #pragma unroll
            for (int i = 0; i < 2; ++i) {
                const int op = tid + i * 256;
                const int r = op >> 3, q = op & 7;
                cpa16(base + mat * AT_MAT + r * AT_STR + q * 16,
                      Km[mat] + (size_t)(kt * 64 + r) * Dsz + q * 8);
            }
        }
        CPA_COMMIT();
    };

    issue_kv(0, 0);
    CPA_WAIT(0);
    __syncthreads();

    float oR[8][4] = {};
    float oI[8][4] = {};
    float mrun0 = -INFINITY, mrun1 = -INFINITY;
    float lrun0 = 0.f, lrun1 = 0.f;
    const float sc = 0.125f * 1.4426950408889634f;

    const uint32_t aoff = (uint32_t)((wid * 16 + (lane & 15)) * AT_STR + (lane >> 4) * 16);
    const uint32_t boff = (uint32_t)(((lane & 7) + ((lane >> 4) << 3)) * AT_STR
                                     + ((lane >> 3) & 1) * 16);
    const uint32_t voff = (uint32_t)((lane & 15) * AT_STR + (lane >> 4) * 16);

    for (int kt = 0; kt < NKT; ++kt) {
        if (kt + 1 < NKT) { issue_kv(kt + 1, (kt + 1) & 1); CPA_WAIT(1); }
        else CPA_WAIT(0);
        __syncthreads();
        const uint32_t kb = sb + AT_QBYTES + (kt & 1) * AT_STAGE;

        float sacc[8][4] = {};
        const int ca[6] = {0, 0, 1, 2, 2, 3};
        const int cb[6] = {0, 1, 0, 2, 3, 2};
        #pragma unroll
        for (int ch = 0; ch < 6; ++ch) {
            const uint32_t qbase = sb + ca[ch] * AT_QMAT + aoff;
            const uint32_t kbase = kb + cb[ch] * AT_MAT + boff;
            #pragma unroll
            for (int ks = 0; ks < 4; ++ks) {
                uint32_t a[4];
                ldsm_x4(a, qbase + ks * 32);
                #pragma unroll
                for (int np = 0; np < 4; ++np) {
                    uint32_t bf[4];
                    ldsm_x4(bf, kbase + np * 16 * AT_STR + ks * 32);
                    mma16816(sacc[2 * np], a, &bf[0]);
                    mma16816(sacc[2 * np + 1], a, &bf[2]);
                }
            }
        }

        float mt0 = -INFINITY, mt1 = -INFINITY;
        #pragma unroll
        for (int j = 0; j < 8; ++j) {
            mt0 = fmaxf(mt0, fmaxf(sacc[j][0], sacc[j][1]));
            mt1 = fmaxf(mt1, fmaxf(sacc[j][2], sacc[j][3]));
        }
        mt0 = fmaxf(mt0, __shfl_xor_sync(0xffffffffu, mt0, 1));
        mt0 = fmaxf(mt0, __shfl_xor_sync(0xffffffffu, mt0, 2));
        mt1 = fmaxf(mt1, __shfl_xor_sync(0xffffffffu, mt1, 1));
        mt1 = fmaxf(mt1, __shfl_xor_sync(0xffffffffu, mt1, 2));
        const float mn0 = fmaxf(mrun0, mt0 * sc);
        const float mn1 = fmaxf(mrun1, mt1 * sc);

        float rs0 = 0.f, rs1 = 0.f;
        uint32_t ph[4][4], pl[4][4];
        #pragma unroll
        for (int j = 0; j < 8; ++j) {
            float p0 = fexp2(fmaf(sacc[j][0], sc, -mn0));
            float p1 = fexp2(fmaf(sacc[j][1], sc, -mn0));
            float p2 = fexp2(fmaf(sacc[j][2], sc, -mn1));
            float p3 = fexp2(fmaf(sacc[j][3], sc, -mn1));
            rs0 += p0 + p1;
            rs1 += p2 + p3;
            __nv_bfloat16 h0, l0, h1, l1, h2, l2, h3, l3;
            split1(p0, h0, l0); split1(p1, h1, l1);
            split1(p2, h2, l2); split1(p3, h3, l3);
            const int ks = j >> 1;
            const int hx = (j & 1) * 2;
            ph[ks][hx + 0] = packbf2(h0, h1);
            ph[ks][hx + 1] = packbf2(h2, h3);
            pl[ks][hx + 0] = packbf2(l0, l1);
            pl[ks][hx + 1] = packbf2(l2, l3);
        }

        rs0 += __shfl_xor_sync(0xffffffffu, rs0, 1);
        rs0 += __shfl_xor_sync(0xffffffffu, rs0, 2);
        rs1 += __shfl_xor_sync(0xffffffffu, rs1, 1);
        rs1 += __shfl_xor_sync(0xffffffffu, rs1, 2);
        const float c0 = fexp2(mrun0 - mn0);
        const float c1 = fexp2(mrun1 - mn1);
        lrun0 = lrun0 * c0 + rs0;
        lrun1 = lrun1 * c1 + rs1;
        mrun0 = mn0; mrun1 = mn1;
        #pragma unroll
        for (int j = 0; j < 8; ++j) {
            oR[j][0] *= c0; oR[j][1] *= c0; oR[j][2] *= c1; oR[j][3] *= c1;
            oI[j][0] *= c0; oI[j][1] *= c0; oI[j][2] *= c1; oI[j][3] *= c1;
        }

        const int pvb[6] = {4, 5, 4, 6, 7, 6};
        #pragma unroll
        for (int ch = 0; ch < 6; ++ch) {
            const uint32_t vbase = kb + pvb[ch] * AT_MAT + voff;
            uint32_t (*pp)[4] = (ch == 2 || ch == 5) ? pl : ph;
            float (*oo)[4] = (ch < 3) ? oR : oI;
            #pragma unroll
            for (int ks = 0; ks < 4; ++ks) {
                #pragma unroll
                for (int np = 0; np < 4; ++np) {
                    uint32_t vb[4];
                    ldsm_x4_t(vb, vbase + ks * 16 * AT_STR + np * 32);
                    mma16816(oo[2 * np], pp[ks], &vb[0]);
                    mma16816(oo[2 * np + 1], pp[ks], &vb[2]);
                }
            }
        }
        __syncthreads();
    }

    const float inv0 = 1.0f / lrun0;
    const float inv1 = 1.0f / lrun1;
    const int b = bh >> 4, h = bh & 15;
    const int row0 = q0 + wid * 16 + (lane >> 2);
    const size_t rbase = (size_t)b * Lsz * Esz;
    #pragma unroll
    for (int j = 0; j < 8; ++j) {
        const int col = h * 64 + j * 8 + (lane & 3) * 2;
        float2 v;
        v.x = oR[j][0] * inv0; v.y = oR[j][1] * inv0;
        *(float2*)&out_r[rbase + (size_t)row0 * Esz + col] = v;
        v.x = oR[j][2] * inv1; v.y = oR[j][3] * inv1;
        *(float2*)&out_r[rbase + (size_t)(row0 + 8) * Esz + col] = v;
        v.x = oI[j][0] * inv0; v.y = oI[j][1] * inv0;
        *(float2*)&out_i[rbase + (size_t)row0 * Esz + col] = v;
        v.x = oI[j][2] * inv1; v.y = oI[j][3] * inv1;
        *(float2*)&out_i[rbase + (size_t)(row0 + 8) * Esz + col] = v;
    }
}

// ---------------------------------------------------------------------------
extern "C" void kernel_launch(void* const* d_in, const int* in_sizes, int n_in,
                              void* d_out, int out_size)
{
    (void)in_sizes; (void)n_in; (void)out_size;
    const float* query_r = (const float*)d_in[0];
    const float* query_i = (const float*)d_in[1];
    const float* key_r   = (const float*)d_in[2];
    const float* key_i   = (const float*)d_in[3];
    const float* value_r = (const float*)d_in[4];
    const float* value_i = (const float*)d_in[5];
    const float* Wq_r = (const float*)d_in[6];
    const float* Wq_i = (const float*)d_in[7];
    const float* bq_r = (const float*)d_in[8];
    const float* bq_i = (const float*)d_in[9];
    const float* Wk_r = (const float*)d_in[10];
    const float* Wk_i = (const float*)d_in[11];
    const float* bk_r = (const float*)d_in[12];
    const float* bk_i = (const float*)d_in[13];
    const float* Wv_r = (const float*)d_in[14];
    const float* Wv_i = (const float*)d_in[15];
    const float* bv_r = (const float*)d_in[16];
    const float* bv_i = (const float*)d_in[17];
    const float* Wo_r = (const float*)d_in[18];
    const float* Wo_i = (const float*)d_in[19];
    const float* bo_r = (const float*)d_in[20];
    const float* bo_i = (const float*)d_in[21];

    float* scratch = nullptr;
    cudaGetSymbolAddress((void**)&scratch, g_scratch);
    int8_t* acat = nullptr;
    cudaGetSymbolAddress((void**)&acat, g_acat);
    int8_t* bq = nullptr;
    cudaGetSymbolAddress((void**)&bq, g_bq);
    __nv_bfloat16* attn = nullptr;
    cudaGetSymbolAddress((void**)&attn, g_attn);
    float* scales = nullptr;
    cudaGetSymbolAddress((void**)&scales, g_scales);

    float* gqr = scratch + 0ull * BLE;
    float* gqi = scratch + 1ull * BLE;
    float* gkr = scratch + 2ull * BLE;
    float* gki = scratch + 3ull * BLE;
    float* gvr = scratch + 4ull * BLE;
    float* gvi = scratch + 5ull * BLE;
    float* gor = scratch + 6ull * BLE;
    float* goi = scratch + 7ull * BLE;

    auto Bq = [&](int layer, int t) {
        return bq + ((size_t)(layer * 4 + t)) * Esz * KA;
    };
    auto At = [&](int s) { return attn + (size_t)s * BHD; };

    zero_scales_kernel<<<1, 32>>>();

    const int WN4 = Esz * Esz / 4;
    const float* Wr_[4] = {Wq_r, Wk_r, Wv_r, Wo_r};
    const float* Wi_[4] = {Wq_i, Wk_i, Wv_i, Wo_i};
    for (int l = 0; l < 4; ++l) {
        absmax_kernel<<<256, 256>>>(Wr_[l], Wi_[l], WN4, scales + l);
        quantW_kernel<<<512, 256>>>(Wr_[l], Wi_[l], scales + l,
                                    Bq(l, 0), Bq(l, 1), Bq(l, 2), Bq(l, 3));
    }

    cudaFuncSetAttribute((const void*)igemm_kernel,
                         cudaFuncAttributeMaxDynamicSharedMemorySize, IGEMM_SMEM);
    dim3 gg(Esz / IGN, NROW / IGM);   // (16, 64)

    const int XN4 = BLE / 4;

    absmax_kernel<<<512, 256>>>(query_r, query_i, XN4, scales + 4);
    quantX_kernel<<<1024, 256>>>(query_r, query_i, scales + 4, acat);
    igemm_kernel<<<gg, 256, IGEMM_SMEM>>>(acat, Bq(0,0), Bq(0,1), Bq(0,2), Bq(0,3),
                                          scales + 4, scales + 0, bq_r, bq_i, gqr, gqi);

    absmax_kernel<<<512, 256>>>(key_r, key_i, XN4, scales + 5);
    quantX_kernel<<<1024, 256>>>(key_r, key_i, scales + 5, acat);
    igemm_kernel<<<gg, 256, IGEMM_SMEM>>>(acat, Bq(1,0), Bq(1,1), Bq(1,2), Bq(1,3),
                                          scales + 5, scales + 1, bk_r, bk_i, gkr, gki);

    absmax_kernel<<<512, 256>>>(value_r, value_i, XN4, scales + 6);
    quantX_kernel<<<1024, 256>>>(value_r, value_i, scales + 6, acat);
    igemm_kernel<<<gg, 256, IGEMM_SMEM>>>(acat, Bq(2,0), Bq(2,1), Bq(2,2), Bq(2,3),
                                          scales + 6, scales + 2, bv_r, bv_i, gvr, gvi);

    attprep_kernel<<<1024, 256>>>(gqr, gqi, At(0), At(1), At(2), At(3));
    attprep_kernel<<<1024, 256>>>(gkr, gki, At(4), At(5), At(6), At(7));
    attprep_kernel<<<1024, 256>>>(gvr, gvi, At(8), At(9), At(10), At(11));

    cudaFuncSetAttribute((const void*)attn_tc_kernel,
                         cudaFuncAttributeMaxDynamicSharedMemorySize, AT_SMEM);
    attn_tc_kernel<<<dim3(Lsz / 128, Bsz * Hsz), 256, AT_SMEM>>>(
        At(0), At(1), At(2), At(3), At(4), At(5), At(6), At(7),
        At(8), At(9), At(10), At(11), gor, goi);

    absmax_kernel<<<512, 256>>>(gor, goi, XN4, scales + 7);
    quantX_kernel<<<1024, 256>>>(gor, goi, scales + 7, acat);
    float* yr = (float*)d_out;
    float* yi = yr + BLE;
    igemm_kernel<<<gg, 256, IGEMM_SMEM>>>(acat, Bq(3,0), Bq(3,1), Bq(3,2), Bq(3,3),
                                          scales + 7, scales + 3, bo_r, bo_i, yr, yi);
}

// round 6
// speedup vs baseline: 2.3957x; 2.3957x over previous
#include <cuda_runtime.h>
#include <cuda_bf16.h>
#include <math.h>
#include <cstdint>

#define Bsz 2
#define Lsz 2048
#define Esz 1024
#define Hsz 16
#define Dsz 64
#define NROW 4096               // Bsz*Lsz
#define BLE  (Bsz*Lsz*Esz)      // 4,194,304
#define KE   6144               // concatenated split-K
#define BHD  ((size_t)Bsz*Hsz*Lsz*Dsz)

// fp32 scratch: or, oi (attention output)
__device__ float g_scratch[2u * BLE];
// concatenated-K A matrices: 3 (q,k,v) + reuse slot 0 for o
__device__ __nv_bfloat16 g_acat[3ull * NROW * KE];            // 150 MB
// weight B matrices: 4 layers x {B1, B2}, each [Esz, KE]
__device__ __nv_bfloat16 g_bcat[8ull * Esz * KE];             // 100 MB
// attention bf16 arrays: q(rh,rl,ih,il) k(4) v(4)
__device__ __nv_bfloat16 g_attn[12ull * BHD];                 // 96 MB

// ---------------------------------------------------------------------------
// helpers
// ---------------------------------------------------------------------------
__device__ __forceinline__ uint32_t smem_u32(const void* p) {
    uint32_t a;
    asm("{ .reg .u64 t; cvta.to.shared.u64 t, %1; cvt.u32.u64 %0, t; }" : "=r"(a) : "l"(p));
    return a;
}
__device__ __forceinline__ void cpa16(uint32_t dst, const void* src) {
    asm volatile("cp.async.cg.shared.global [%0], [%1], 16;" :: "r"(dst), "l"(src));
}
#define CPA_COMMIT() asm volatile("cp.async.commit_group;" ::: "memory")
#define CPA_WAIT(n)  asm volatile("cp.async.wait_group %0;" :: "n"(n) : "memory")

__device__ __forceinline__ void ldsm_x4(uint32_t* r, uint32_t addr) {
    asm volatile("ldmatrix.sync.aligned.m8n8.x4.shared.b16 {%0,%1,%2,%3}, [%4];"
        : "=r"(r[0]), "=r"(r[1]), "=r"(r[2]), "=r"(r[3]) : "r"(addr));
}
__device__ __forceinline__ void ldsm_x4_t(uint32_t* r, uint32_t addr) {
    asm volatile("ldmatrix.sync.aligned.m8n8.x4.trans.shared.b16 {%0,%1,%2,%3}, [%4];"
        : "=r"(r[0]), "=r"(r[1]), "=r"(r[2]), "=r"(r[3]) : "r"(addr));
}
__device__ __forceinline__ void mma16816(float* c, const uint32_t* a, const uint32_t* b) {
    asm volatile("mma.sync.aligned.m16n8k16.row.col.f32.bf16.bf16.f32 "
        "{%0,%1,%2,%3}, {%4,%5,%6,%7}, {%8,%9}, {%0,%1,%2,%3};"
        : "+f"(c[0]), "+f"(c[1]), "+f"(c[2]), "+f"(c[3])
        : "r"(a[0]), "r"(a[1]), "r"(a[2]), "r"(a[3]), "r"(b[0]), "r"(b[1]));
}
__device__ __forceinline__ float fexp2(float x) {
    float y;
    asm("ex2.approx.ftz.f32 %0, %1;" : "=f"(y) : "f"(x));
    return y;
}
__device__ __forceinline__ void split1(float x, __nv_bfloat16& h, __nv_bfloat16& l) {
    h = __float2bfloat16(x);
    l = __float2bfloat16(x - __bfloat162float(h));
}
__device__ __forceinline__ uint32_t packbf2(__nv_bfloat16 a, __nv_bfloat16 b) {
    __nv_bfloat162 t; t.x = a; t.y = b;
    return *(uint32_t*)&t;
}
__device__ __forceinline__ void store4(__nv_bfloat16* p, __nv_bfloat16 a, __nv_bfloat16 b,
                                       __nv_bfloat16 c, __nv_bfloat16 d) {
    uint2 w;
    w.x = packbf2(a, b); w.y = packbf2(c, d);
    *(uint2*)p = w;
}

// ---------------------------------------------------------------------------
// split kernels: concatenated-K operands
// A_cat blocks: [Xr_h | Xr_h | Xr_l | Xi_h | Xi_h | Xi_l]
// ---------------------------------------------------------------------------
__global__ __launch_bounds__(256) void splitA_kernel(
    const float* __restrict__ Xr, const float* __restrict__ Xi,
    __nv_bfloat16* __restrict__ A)
{
    const int total = NROW * Esz / 4;
    int idx = blockIdx.x * 256 + threadIdx.x;
    const int stride = gridDim.x * 256;
    for (; idx < total; idx += stride) {
        const int m = idx >> 8;
        const int kq = (idx & 255) << 2;
        float4 xr = ((const float4*)Xr)[idx];
        float4 xi = ((const float4*)Xi)[idx];
        __nv_bfloat16 rh[4], rl[4], ih[4], il[4];
        split1(xr.x, rh[0], rl[0]); split1(xr.y, rh[1], rl[1]);
        split1(xr.z, rh[2], rl[2]); split1(xr.w, rh[3], rl[3]);
        split1(xi.x, ih[0], il[0]); split1(xi.y, ih[1], il[1]);
        split1(xi.z, ih[2], il[2]); split1(xi.w, ih[3], il[3]);
        __nv_bfloat16* base = A + (size_t)m * KE + kq;
        store4(base + 0,    rh[0], rh[1], rh[2], rh[3]);
        store4(base + 1024, rh[0], rh[1], rh[2], rh[3]);
        store4(base + 2048, rl[0], rl[1], rl[2], rl[3]);
        store4(base + 3072, ih[0], ih[1], ih[2], ih[3]);
        store4(base + 4096, ih[0], ih[1], ih[2], ih[3]);
        store4(base + 5120, il[0], il[1], il[2], il[3]);
    }
}

__global__ __launch_bounds__(256) void splitW_kernel(
    const float* __restrict__ Wr, const float* __restrict__ Wi,
    __nv_bfloat16* __restrict__ B1, __nv_bfloat16* __restrict__ B2)
{
    const int total = Esz * Esz / 4;
    int idx = blockIdx.x * 256 + threadIdx.x;
    const int stride = gridDim.x * 256;
    for (; idx < total; idx += stride) {
        const int n = idx >> 8;
        const int kq = (idx & 255) << 2;
        float4 wr = ((const float4*)Wr)[idx];
        float4 wi = ((const float4*)Wi)[idx];
        __nv_bfloat16 rh[4], rl[4], ih[4], il[4], nh[4], nl[4];
        split1(wr.x, rh[0], rl[0]); split1(wr.y, rh[1], rl[1]);
        split1(wr.z, rh[2], rl[2]); split1(wr.w, rh[3], rl[3]);
        split1(wi.x, ih[0], il[0]); split1(wi.y, ih[1], il[1]);
        split1(wi.z, ih[2], il[2]); split1(wi.w, ih[3], il[3]);
        split1(-wi.x, nh[0], nl[0]); split1(-wi.y, nh[1], nl[1]);
        split1(-wi.z, nh[2], nl[2]); split1(-wi.w, nh[3], nl[3]);
        __nv_bfloat16* b1 = B1 + (size_t)n * KE + kq;
        __nv_bfloat16* b2 = B2 + (size_t)n * KE + kq;
        store4(b1 + 0,    rh[0], rh[1], rh[2], rh[3]);
        store4(b1 + 1024, rl[0], rl[1], rl[2], rl[3]);
        store4(b1 + 2048, rh[0], rh[1], rh[2], rh[3]);
        store4(b1 + 3072, nh[0], nh[1], nh[2], nh[3]);
        store4(b1 + 4096, nl[0], nl[1], nl[2], nl[3]);
        store4(b1 + 5120, nh[0], nh[1], nh[2], nh[3]);
        store4(b2 + 0,    ih[0], ih[1], ih[2], ih[3]);
        store4(b2 + 1024, il[0], il[1], il[2], il[3]);
        store4(b2 + 2048, ih[0], ih[1], ih[2], ih[3]);
        store4(b2 + 3072, rh[0], rh[1], rh[2], rh[3]);
        store4(b2 + 4096, rl[0], rl[1], rl[2], rl[3]);
        store4(b2 + 5120, rh[0], rh[1], rh[2], rh[3]);
    }
}

// ---------------------------------------------------------------------------
// GEMM common config: CTA 128x128, K-chunk 64, 3-stage cp.async, mma.sync bf16
// ---------------------------------------------------------------------------
#define GM 128
#define GN 128
#define KCH 64
#define NCHK (KE / KCH)                 // 96
#define ASTR 144
#define A_BYTES (GM * ASTR)
#define B_BYTES (GN * ASTR)
#define STAGE (A_BYTES + 2 * B_BYTES)   // 55296
#define GEMM_SMEM (3 * STAGE)           // 165888

struct QKVBatch {
    const __nv_bfloat16* A[3];
    const __nv_bfloat16* B1[3];
    const __nv_bfloat16* B2[3];
    const float* br[3];
    const float* bi[3];
    __nv_bfloat16* RH[3];
    __nv_bfloat16* RL[3];
    __nv_bfloat16* IH[3];
    __nv_bfloat16* IL[3];
};

// shared mainloop body (templated on epilogue via flag)
__device__ __forceinline__ void gemm_mainloop(
    uint32_t sb, int tid, int m0, int n0,
    const __nv_bfloat16* A, const __nv_bfloat16* B1, const __nv_bfloat16* B2,
    float acc[2][4][4][4])
{
    const int lane = tid & 31;
    const int wid = tid >> 5;
    const int wm = wid >> 2;
    const int wn = wid & 3;

    auto load_chunk = [&](int c, int buf) {
        const uint32_t s = sb + buf * STAGE;
        const int kc = c * KCH;
        #pragma unroll
        for (int i = 0; i < 4; ++i) {
            const int op = tid + i * 256;
            const int r = op >> 3, q = op & 7;
            cpa16(s + r * ASTR + q * 16, A + (size_t)(m0 + r) * KE + kc + q * 8);
        }
        #pragma unroll
        for (int i = 0; i < 4; ++i) {
            const int op = tid + i * 256;
            const int r = op >> 3, q = op & 7;
            cpa16(s + A_BYTES + r * ASTR + q * 16,
                  B1 + (size_t)(n0 + r) * KE + kc + q * 8);
            cpa16(s + A_BYTES + B_BYTES + r * ASTR + q * 16,
                  B2 + (size_t)(n0 + r) * KE + kc + q * 8);
        }
        CPA_COMMIT();
    };

    const uint32_t aRowOff = (uint32_t)(wm * 64 + (lane & 15));
    const uint32_t aColB   = (uint32_t)((lane >> 4) * 16);
    const uint32_t bRowOff = (uint32_t)(wn * 32 + (lane & 7) + ((lane >> 4) << 3));
    const uint32_t bColB   = (uint32_t)(((lane >> 3) & 1) * 16);

    load_chunk(0, 0);
    load_chunk(1, 1);

    int buf = 0;
    for (int c = 0; c < NCHK; ++c) {
        if (c + 2 < NCHK) { load_chunk(c + 2, (buf + 2) % 3); CPA_WAIT(2); }
        else if (c + 1 < NCHK) CPA_WAIT(1);
        else CPA_WAIT(0);
        __syncthreads();

        const uint32_t s = sb + buf * STAGE;
        const uint32_t aB = s + aRowOff * ASTR + aColB;
        const uint32_t bB = s + A_BYTES + bRowOff * ASTR + bColB;

        #pragma unroll
        for (int ks = 0; ks < 4; ++ks) {
            uint32_t a[4][4];
            #pragma unroll
            for (int mt = 0; mt < 4; ++mt)
                ldsm_x4(a[mt], aB + mt * 16 * ASTR + ks * 32);
            uint32_t bf[2][2][4];
            #pragma unroll
            for (int o = 0; o < 2; ++o)
                #pragma unroll
                for (int np = 0; np < 2; ++np)
                    ldsm_x4(bf[o][np], bB + o * B_BYTES + np * 16 * ASTR + ks * 32);
            #pragma unroll
            for (int o = 0; o < 2; ++o)
                #pragma unroll
                for (int mt = 0; mt < 4; ++mt)
                    #pragma unroll
                    for (int nt = 0; nt < 4; ++nt)
                        mma16816(acc[o][mt][nt], a[mt], &bf[o][nt >> 1][(nt & 1) * 2]);
        }
        __syncthreads();
        buf = (buf + 1) % 3;
    }
}

// q/k/v batched GEMM: epilogue writes bf16 hi/lo directly in [BH][L][D]
__global__ __launch_bounds__(256, 1) void gemm_qkv_kernel(QKVBatch p)
{
    extern __shared__ char smem[];
    const uint32_t sb = smem_u32(smem);
    const int tid = threadIdx.x;
    const int lane = tid & 31;
    const int wid = tid >> 5;
    const int wm = wid >> 2;
    const int wn = wid & 3;
    const int m0 = blockIdx.y * GM;
    const int n0 = blockIdx.x * GN;
    const int z = blockIdx.z;

    float acc[2][4][4][4] = {};
    gemm_mainloop(sb, tid, m0, n0, p.A[z], p.B1[z], p.B2[z], acc);

    const float* br = p.br[z];
    const float* bi = p.bi[z];
    __nv_bfloat16* RH = p.RH[z];
    __nv_bfloat16* RL = p.RL[z];
    __nv_bfloat16* IH = p.IH[z];
    __nv_bfloat16* IL = p.IL[z];

    const int rowb = m0 + wm * 64 + (lane >> 2);
    const int colb = n0 + wn * 32 + (lane & 3) * 2;
    #pragma unroll
    for (int mt = 0; mt < 4; ++mt) {
        #pragma unroll
        for (int nt = 0; nt < 4; ++nt) {
            const int col = colb + nt * 8;
            const float br0 = __ldg(&br[col]), br1 = __ldg(&br[col + 1]);
            const float bi0 = __ldg(&bi[col]), bi1 = __ldg(&bi[col + 1]);
            const int h = col >> 6, d = col & 63;
            #pragma unroll
            for (int hf = 0; hf < 2; ++hf) {
                const int row = rowb + mt * 16 + hf * 8;
                const int f = hf * 2;
                const int b = row >> 11, l = row & 2047;
                const size_t o = (((size_t)(b * Hsz + h) * Lsz) + l) * Dsz + d;
                float yr0 = acc[0][mt][nt][f]   + br0;
                float yr1 = acc[0][mt][nt][f+1] + br1;
                float yi0 = acc[1][mt][nt][f]   + bi0;
                float yi1 = acc[1][mt][nt][f+1] + bi1;
                __nv_bfloat16 h0, l0, h1, l1;
                split1(yr0, h0, l0); split1(yr1, h1, l1);
                *(uint32_t*)&RH[o] = packbf2(h0, h1);
                *(uint32_t*)&RL[o] = packbf2(l0, l1);
                split1(yi0, h0, l0); split1(yi1, h1, l1);
                *(uint32_t*)&IH[o] = packbf2(h0, h1);
                *(uint32_t*)&IL[o] = packbf2(l0, l1);
            }
        }
    }
}

// output-layer GEMM: fp32 epilogue to [B,L,E]
__global__ __launch_bounds__(256, 1) void gemm_kernel(
    const __nv_bfloat16* __restrict__ A,
    const __nv_bfloat16* __restrict__ B1,
    const __nv_bfloat16* __restrict__ B2,
    const float* __restrict__ br, const float* __restrict__ bi,
    float* __restrict__ Yr, float* __restrict__ Yi)
{
    extern __shared__ char smem[];
    const uint32_t sb = smem_u32(smem);
    const int tid = threadIdx.x;
    const int lane = tid & 31;
    const int wid = tid >> 5;
    const int wm = wid >> 2;
    const int wn = wid & 3;
    const int m0 = blockIdx.y * GM;
    const int n0 = blockIdx.x * GN;

    float acc[2][4][4][4] = {};
    gemm_mainloop(sb, tid, m0, n0, A, B1, B2, acc);

    const int rowb = m0 + wm * 64 + (lane >> 2);
    const int colb = n0 + wn * 32 + (lane & 3) * 2;
    #pragma unroll
    for (int mt = 0; mt < 4; ++mt) {
        #pragma unroll
        for (int nt = 0; nt < 4; ++nt) {
            const int col = colb + nt * 8;
            const int row = rowb + mt * 16;
            const float br0 = __ldg(&br[col]), br1 = __ldg(&br[col + 1]);
            const float bi0 = __ldg(&bi[col]), bi1 = __ldg(&bi[col + 1]);
            float2 v;
            v.x = acc[0][mt][nt][0] + br0; v.y = acc[0][mt][nt][1] + br1;
            *(float2*)&Yr[(size_t)row * Esz + col] = v;
            v.x = acc[0][mt][nt][2] + br0; v.y = acc[0][mt][nt][3] + br1;
            *(float2*)&Yr[(size_t)(row + 8) * Esz + col] = v;
            v.x = acc[1][mt][nt][0] + bi0; v.y = acc[1][mt][nt][1] + bi1;
            *(float2*)&Yi[(size_t)row * Esz + col] = v;
            v.x = acc[1][mt][nt][2] + bi0; v.y = acc[1][mt][nt][3] + bi1;
            *(float2*)&Yi[(size_t)(row + 8) * Esz + col] = v;
        }
    }
}

// ---------------------------------------------------------------------------
// Tensor-core flash attention (bf16 hi/lo) with ldsm fragment reuse.
// ---------------------------------------------------------------------------
#define AT_STR 144
#define AT_MAT (64 * AT_STR)
#define AT_QMAT (128 * AT_STR)
#define AT_QBYTES (4 * AT_QMAT)
#define AT_STAGE (8 * AT_MAT)
#define AT_SMEM (AT_QBYTES + 2 * AT_STAGE)
#define NKT (Lsz / 64)

__global__ __launch_bounds__(256, 1) void attn_tc_kernel(
    const __nv_bfloat16* __restrict__ QRH, const __nv_bfloat16* __restrict__ QRL,
    const __nv_bfloat16* __restrict__ QIH, const __nv_bfloat16* __restrict__ QIL,
    const __nv_bfloat16* __restrict__ KRH, const __nv_bfloat16* __restrict__ KRL,
    const __nv_bfloat16* __restrict__ KIH, const __nv_bfloat16* __restrict__ KIL,
    const __nv_bfloat16* __restrict__ VRH, const __nv_bfloat16* __restrict__ VRL,
    const __nv_bfloat16* __restrict__ VIH, const __nv_bfloat16* __restrict__ VIL,
    float* __restrict__ out_r, float* __restrict__ out_i)
{
    extern __shared__ char smem[];
    const uint32_t sb = smem_u32(smem);
    const int tid = threadIdx.x;
    const int lane = tid & 31;
    const int wid = tid >> 5;
    const int q0 = blockIdx.x * 128;
    const int bh = blockIdx.y;
    const size_t pb = (size_t)bh * Lsz * Dsz;

    const __nv_bfloat16* Qm[4] = {QRH + pb, QRL + pb, QIH + pb, QIL + pb};
    const __nv_bfloat16* Km[8] = {KRH + pb, KRL + pb, KIH + pb, KIL + pb,
                                  VRH + pb, VRL + pb, VIH + pb, VIL + pb};

    #pragma unroll
    for (int mat = 0; mat < 4; ++mat) {
        #pragma unroll
        for (int i = 0; i < 4; ++i) {
            const int op = tid + i * 256;
            const int r = op >> 3, q = op & 7;
            cpa16(sb + mat * AT_QMAT + r * AT_STR + q * 16,
                  Qm[mat] + (size_t)(q0 + r) * Dsz + q * 8);
        }
    }
    CPA_COMMIT();

    auto issue_kv = [&](int kt, int buf) {
        const uint32_t base = sb + AT_QBYTES + buf * AT_STAGE;
        #pragma unroll
        for (int mat = 0; mat < 8; ++mat) {
            #pragma unroll
            for (int i = 0; i < 2; ++i) {
                const int op = tid + i * 256;
                const int r = op >> 3, q = op & 7;
                cpa16(base + mat * AT_MAT + r * AT_STR + q * 16,
                      Km[mat] + (size_t)(kt * 64 + r) * Dsz + q * 8);
            }
        }
        CPA_COMMIT();
    };

    issue_kv(0, 0);
    CPA_WAIT(0);
    __syncthreads();

    float oR[8][4] = {};
    float oI[8][4] = {};
    float mrun0 = -INFINITY, mrun1 = -INFINITY;
    float lrun0 = 0.f, lrun1 = 0.f;
    const float sc = 0.125f * 1.4426950408889634f;

    const uint32_t aoff = (uint32_t)((wid * 16 + (lane & 15)) * AT_STR + (lane >> 4) * 16);
    const uint32_t boff = (uint32_t)(((lane & 7) + ((lane >> 4) << 3)) * AT_STR
                                     + ((lane >> 3) & 1) * 16);
    const uint32_t voff = (uint32_t)((lane & 15) * AT_STR + (lane >> 4) * 16);

    for (int kt = 0; kt < NKT; ++kt) {
        if (kt + 1 < NKT) { issue_kv(kt + 1, (kt + 1) & 1); CPA_WAIT(1); }
        else CPA_WAIT(0);
        __syncthreads();
        const uint32_t kb = sb + AT_QBYTES + (kt & 1) * AT_STAGE;

        // ---- scores: load each fragment once, fire all 6 chains on it ----
        float sacc[8][4] = {};
        #pragma unroll
        for (int ks = 0; ks < 4; ++ks) {
            uint32_t aq[4][4];
            #pragma unroll
            for (int m = 0; m < 4; ++m)
                ldsm_x4(aq[m], sb + m * AT_QMAT + aoff + ks * 32);
            #pragma unroll
            for (int np = 0; np < 4; ++np) {
                uint32_t kf[4][4];
                #pragma unroll
                for (int m = 0; m < 4; ++m)
                    ldsm_x4(kf[m], kb + m * AT_MAT + boff + np * 16 * AT_STR + ks * 32);
                // chains: q0k0 q0k1 q1k0 q2k2 q2k3 q3k2
                mma16816(sacc[2*np],   aq[0], &kf[0][0]);
                mma16816(sacc[2*np+1], aq[0], &kf[0][2]);
                mma16816(sacc[2*np],   aq[0], &kf[1][0]);
                mma16816(sacc[2*np+1], aq[0], &kf[1][2]);
                mma16816(sacc[2*np],   aq[1], &kf[0][0]);
                mma16816(sacc[2*np+1], aq[1], &kf[0][2]);
                mma16816(sacc[2*np],   aq[2], &kf[2][0]);
                mma16816(sacc[2*np+1], aq[2], &kf[2][2]);
                mma16816(sacc[2*np],   aq[2], &kf[3][0]);
                mma16816(sacc[2*np+1], aq[2], &kf[3][2]);
                mma16816(sacc[2*np],   aq[3], &kf[2][0]);
                mma16816(sacc[2*np+1], aq[3], &kf[2][2]);
            }
        }

        // ---- online softmax ----
        float mt0 = -INFINITY, mt1 = -INFINITY;
        #pragma unroll
        for (int j = 0; j < 8; ++j) {
            mt0 = fmaxf(mt0, fmaxf(sacc[j][0], sacc[j][1]));
            mt1 = fmaxf(mt1, fmaxf(sacc[j][2], sacc[j][3]));
        }
        mt0 = fmaxf(mt0, __shfl_xor_sync(0xffffffffu, mt0, 1));
        mt0 = fmaxf(mt0, __shfl_xor_sync(0xffffffffu, mt0, 2));
        mt1 = fmaxf(mt1, __shfl_xor_sync(0xffffffffu, mt1, 1));
        mt1 = fmaxf(mt1, __shfl_xor_sync(0xffffffffu, mt1, 2));
        const float mn0 = fmaxf(mrun0, mt0 * sc);
        const float mn1 = fmaxf(mrun1, mt1 * sc);

        float rs0 = 0.f, rs1 = 0.f;
        uint32_t ph[4][4], pl[4][4];
        #pragma unroll
        for (int j = 0; j < 8; ++j) {
            float p0 = fexp2(fmaf(sacc[j][0], sc, -mn0));
            float p1 = fexp2(fmaf(sacc[j][1], sc, -mn0));
            float p2 = fexp2(fmaf(sacc[j][2], sc, -mn1));
            float p3 = fexp2(fmaf(sacc[j][3], sc, -mn1));
            rs0 += p0 + p1;
            rs1 += p2 + p3;
            __nv_bfloat16 h0, l0, h1, l1, h2, l2, h3, l3;
            split1(p0, h0, l0); split1(p1, h1, l1);
            split1(p2, h2, l2); split1(p3, h3, l3);
            const int ks = j >> 1;
            const int hx = (j & 1) * 2;
            ph[ks][hx + 0] = packbf2(h0, h1);
            ph[ks][hx + 1] = packbf2(h2, h3);
            pl[ks][hx + 0] = packbf2(l0, l1);
            pl[ks][hx + 1] = packbf2(l2, l3);
        }

        rs0 += __shfl_xor_sync(0xffffffffu, rs0, 1);
        rs0 += __shfl_xor_sync(0xffffffffu, rs0, 2);
        rs1 += __shfl_xor_sync(0xffffffffu, rs1, 1);
        rs1 += __shfl_xor_sync(0xffffffffu, rs1, 2);
        const float c0 = fexp2(mrun0 - mn0);
        const float c1 = fexp2(mrun1 - mn1);
        lrun0 = lrun0 * c0 + rs0;
        lrun1 = lrun1 * c1 + rs1;
        mrun0 = mn0; mrun1 = mn1;
        #pragma unroll
        for (int j = 0; j < 8; ++j) {
            oR[j][0] *= c0; oR[j][1] *= c0; oR[j][2] *= c1; oR[j][3] *= c1;
            oI[j][0] *= c0; oI[j][1] *= c0; oI[j][2] *= c1; oI[j][3] *= c1;
        }

        // ---- O += P @ V : load each V fragment once, 6 chains per frag set ----
        #pragma unroll
        for (int ks = 0; ks < 4; ++ks) {
            #pragma unroll
            for (int np = 0; np < 4; ++np) {
                uint32_t vf[4][4];
                #pragma unroll
                for (int m = 0; m < 4; ++m)
                    ldsm_x4_t(vf[m], kb + (4 + m) * AT_MAT + voff
                                       + ks * 16 * AT_STR + np * 32);
                mma16816(oR[2*np],   ph[ks], &vf[0][0]);
                mma16816(oR[2*np+1], ph[ks], &vf[0][2]);
                mma16816(oR[2*np],   ph[ks], &vf[1][0]);
                mma16816(oR[2*np+1], ph[ks], &vf[1][2]);
                mma16816(oR[2*np],   pl[ks], &vf[0][0]);
                mma16816(oR[2*np+1], pl[ks], &vf[0][2]);
                mma16816(oI[2*np],   ph[ks], &vf[2][0]);
                mma16816(oI[2*np+1], ph[ks], &vf[2][2]);
                mma16816(oI[2*np],   ph[ks], &vf[3][0]);
                mma16816(oI[2*np+1], ph[ks], &vf[3][2]);
                mma16816(oI[2*np],   pl[ks], &vf[2][0]);
                mma16816(oI[2*np+1], pl[ks], &vf[2][2]);
            }
        }
        __syncthreads();
    }

    const float inv0 = 1.0f / lrun0;
    const float inv1 = 1.0f / lrun1;
    const int b = bh >> 4, h = bh & 15;
    const int row0 = q0 + wid * 16 + (lane >> 2);
    const size_t rbase = (size_t)b * Lsz * Esz;
    #pragma unroll
    for (int j = 0; j < 8; ++j) {
        const int col = h * 64 + j * 8 + (lane & 3) * 2;
        float2 v;
        v.x = oR[j][0] * inv0; v.y = oR[j][1] * inv0;
        *(float2*)&out_r[rbase + (size_t)row0 * Esz + col] = v;
        v.x = oR[j][2] * inv1; v.y = oR[j][3] * inv1;
        *(float2*)&out_r[rbase + (size_t)(row0 + 8) * Esz + col] = v;
        v.x = oI[j][0] * inv0; v.y = oI[j][1] * inv0;
        *(float2*)&out_i[rbase + (size_t)row0 * Esz + col] = v;
        v.x = oI[j][2] * inv1; v.y = oI[j][3] * inv1;
        *(float2*)&out_i[rbase + (size_t)(row0 + 8) * Esz + col] = v;
    }
}

// ---------------------------------------------------------------------------
extern "C" void kernel_launch(void* const* d_in, const int* in_sizes, int n_in,
                              void* d_out, int out_size)
{
    (void)in_sizes; (void)n_in; (void)out_size;
    const float* query_r = (const float*)d_in[0];
    const float* query_i = (const float*)d_in[1];
    const float* key_r   = (const float*)d_in[2];
    const float* key_i   = (const float*)d_in[3];
    const float* value_r = (const float*)d_in[4];
    const float* value_i = (const float*)d_in[5];
    const float* Wq_r = (const float*)d_in[6];
    const float* Wq_i = (const float*)d_in[7];
    const float* bq_r = (const float*)d_in[8];
    const float* bq_i = (const float*)d_in[9];
    const float* Wk_r = (const float*)d_in[10];
    const float* Wk_i = (const float*)d_in[11];
    const float* bk_r = (const float*)d_in[12];
    const float* bk_i = (const float*)d_in[13];
    const float* Wv_r = (const float*)d_in[14];
    const float* Wv_i = (const float*)d_in[15];
    const float* bv_r = (const float*)d_in[16];
    const float* bv_i = (const float*)d_in[17];
    const float* Wo_r = (const float*)d_in[18];
    const float* Wo_i = (const float*)d_in[19];
    const float* bo_r = (const float*)d_in[20];
    const float* bo_i = (const float*)d_in[21];

    float* scratch = nullptr;
    cudaGetSymbolAddress((void**)&scratch, g_scratch);
    __nv_bfloat16* acat = nullptr;
    cudaGetSymbolAddress((void**)&acat, g_acat);
    __nv_bfloat16* bcat = nullptr;
    cudaGetSymbolAddress((void**)&bcat, g_bcat);
    __nv_bfloat16* attn = nullptr;
    cudaGetSymbolAddress((void**)&attn, g_attn);

    float* gor = scratch + 0ull * BLE;
    float* goi = scratch + 1ull * BLE;

    auto Wc = [&](int s) { return bcat + (size_t)s * Esz * KE; };
    auto Ac = [&](int s) { return acat + (size_t)s * NROW * KE; };
    auto At = [&](int s) { return attn + (size_t)s * BHD; };

    // weight splits: slots {0,1}=q {2,3}=k {4,5}=v {6,7}=o
    splitW_kernel<<<512, 256>>>(Wq_r, Wq_i, Wc(0), Wc(1));
    splitW_kernel<<<512, 256>>>(Wk_r, Wk_i, Wc(2), Wc(3));
    splitW_kernel<<<512, 256>>>(Wv_r, Wv_i, Wc(4), Wc(5));
    splitW_kernel<<<512, 256>>>(Wo_r, Wo_i, Wc(6), Wc(7));

    // input splits
    splitA_kernel<<<1024, 256>>>(query_r, query_i, Ac(0));
    splitA_kernel<<<1024, 256>>>(key_r,   key_i,   Ac(1));
    splitA_kernel<<<1024, 256>>>(value_r, value_i, Ac(2));

    // batched q/k/v GEMM, bf16 [BH][L][D] outputs
    QKVBatch batch;
    batch.A[0] = Ac(0); batch.A[1] = Ac(1); batch.A[2] = Ac(2);
    batch.B1[0] = Wc(0); batch.B2[0] = Wc(1);
    batch.B1[1] = Wc(2); batch.B2[1] = Wc(3);
    batch.B1[2] = Wc(4); batch.B2[2] = Wc(5);
    batch.br[0] = bq_r; batch.bi[0] = bq_i;
    batch.br[1] = bk_r; batch.bi[1] = bk_i;
    batch.br[2] = bv_r; batch.bi[2] = bv_i;
    for (int z = 0; z < 3; ++z) {
        batch.RH[z] = At(4 * z + 0);
        batch.RL[z] = At(4 * z + 1);
        batch.IH[z] = At(4 * z + 2);
        batch.IL[z] = At(4 * z + 3);
    }

    cudaFuncSetAttribute((const void*)gemm_qkv_kernel,
                         cudaFuncAttributeMaxDynamicSharedMemorySize, GEMM_SMEM);
    cudaFuncSetAttribute((const void*)gemm_kernel,
                         cudaFuncAttributeMaxDynamicSharedMemorySize, GEMM_SMEM);

    gemm_qkv_kernel<<<dim3(Esz / GN, NROW / GM, 3), 256, GEMM_SMEM>>>(batch);

    cudaFuncSetAttribute((const void*)attn_tc_kernel,
                         cudaFuncAttributeMaxDynamicSharedMemorySize, AT_SMEM);
    attn_tc_kernel<<<dim3(Lsz / 128, Bsz * Hsz), 256, AT_SMEM>>>(
        At(0), At(1), At(2), At(3), At(4), At(5), At(6), At(7),
        At(8), At(9), At(10), At(11), gor, goi);

    splitA_kernel<<<1024, 256>>>(gor, goi, Ac(0));
    float* yr = (float*)d_out;
    float* yi = yr + BLE;
    gemm_kernel<<<dim3(Esz / GN, NROW / GM), 256, GEMM_SMEM>>>(
        Ac(0), Wc(6), Wc(7), bo_r, bo_i, yr, yi);
}

// round 7
// speedup vs baseline: 2.4590x; 1.0265x over previous
#include <cuda_runtime.h>
#include <cuda_bf16.h>
#include <cuda_fp16.h>
#include <math.h>
#include <cstdint>

#define Bsz 2
#define Lsz 2048
#define Esz 1024
#define Hsz 16
#define Dsz 64
#define NROW 4096               // Bsz*Lsz
#define BLE  (Bsz*Lsz*Esz)      // 4,194,304
#define KE   6144               // concatenated split-K
#define BHD  ((size_t)Bsz*Hsz*Lsz*Dsz)

// concatenated-K A matrices: q,k,v ; slot 0 reused for attention output
__device__ __nv_bfloat16 g_acat[3ull * NROW * KE];            // 150 MB
// weight B matrices: 4 layers x {B1, B2}, each [Esz, KE]
__device__ __nv_bfloat16 g_bcat[8ull * Esz * KE];             // 100 MB
// attention arrays: q(rh,rl,ih,il) k(4) bf16 ; v(4) fp16
__device__ __nv_bfloat16 g_attn[12ull * BHD];                 // 96 MB

// ---------------------------------------------------------------------------
// helpers
// ---------------------------------------------------------------------------
__device__ __forceinline__ uint32_t smem_u32(const void* p) {
    uint32_t a;
    asm("{ .reg .u64 t; cvta.to.shared.u64 t, %1; cvt.u32.u64 %0, t; }" : "=r"(a) : "l"(p));
    return a;
}
__device__ __forceinline__ void cpa16(uint32_t dst, const void* src) {
    asm volatile("cp.async.cg.shared.global [%0], [%1], 16;" :: "r"(dst), "l"(src));
}
#define CPA_COMMIT() asm volatile("cp.async.commit_group;" ::: "memory")
#define CPA_WAIT(n)  asm volatile("cp.async.wait_group %0;" :: "n"(n) : "memory")

__device__ __forceinline__ void ldsm_x4(uint32_t* r, uint32_t addr) {
    asm volatile("ldmatrix.sync.aligned.m8n8.x4.shared.b16 {%0,%1,%2,%3}, [%4];"
        : "=r"(r[0]), "=r"(r[1]), "=r"(r[2]), "=r"(r[3]) : "r"(addr));
}
__device__ __forceinline__ void ldsm_x4_t(uint32_t* r, uint32_t addr) {
    asm volatile("ldmatrix.sync.aligned.m8n8.x4.trans.shared.b16 {%0,%1,%2,%3}, [%4];"
        : "=r"(r[0]), "=r"(r[1]), "=r"(r[2]), "=r"(r[3]) : "r"(addr));
}
__device__ __forceinline__ void mma16816(float* c, const uint32_t* a, const uint32_t* b) {
    asm volatile("mma.sync.aligned.m16n8k16.row.col.f32.bf16.bf16.f32 "
        "{%0,%1,%2,%3}, {%4,%5,%6,%7}, {%8,%9}, {%0,%1,%2,%3};"
        : "+f"(c[0]), "+f"(c[1]), "+f"(c[2]), "+f"(c[3])
        : "r"(a[0]), "r"(a[1]), "r"(a[2]), "r"(a[3]), "r"(b[0]), "r"(b[1]));
}
__device__ __forceinline__ void mma16816h(float* c, const uint32_t* a, const uint32_t* b) {
    asm volatile("mma.sync.aligned.m16n8k16.row.col.f32.f16.f16.f32 "
        "{%0,%1,%2,%3}, {%4,%5,%6,%7}, {%8,%9}, {%0,%1,%2,%3};"
        : "+f"(c[0]), "+f"(c[1]), "+f"(c[2]), "+f"(c[3])
        : "r"(a[0]), "r"(a[1]), "r"(a[2]), "r"(a[3]), "r"(b[0]), "r"(b[1]));
}
__device__ __forceinline__ float fexp2(float x) {
    float y;
    asm("ex2.approx.ftz.f32 %0, %1;" : "=f"(y) : "f"(x));
    return y;
}
__device__ __forceinline__ void split1(float x, __nv_bfloat16& h, __nv_bfloat16& l) {
    h = __float2bfloat16(x);
    l = __float2bfloat16(x - __bfloat162float(h));
}
__device__ __forceinline__ uint32_t packbf2(__nv_bfloat16 a, __nv_bfloat16 b) {
    __nv_bfloat162 t; t.x = a; t.y = b;
    return *(uint32_t*)&t;
}
__device__ __forceinline__ uint32_t packh2(float a, float b) {
    __half2 t = __floats2half2_rn(a, b);
    return *(uint32_t*)&t;
}
__device__ __forceinline__ void store4(__nv_bfloat16* p, __nv_bfloat16 a, __nv_bfloat16 b,
                                       __nv_bfloat16 c, __nv_bfloat16 d) {
    uint2 w;
    w.x = packbf2(a, b); w.y = packbf2(c, d);
    *(uint2*)p = w;
}

// ---------------------------------------------------------------------------
// split kernels: concatenated-K operands
// A_cat blocks: [Xr_h | Xr_h | Xr_l | Xi_h | Xi_h | Xi_l]
// ---------------------------------------------------------------------------
__global__ __launch_bounds__(256) void splitA_kernel(
    const float* __restrict__ Xr, const float* __restrict__ Xi,
    __nv_bfloat16* __restrict__ A)
{
    const int total = NROW * Esz / 4;
    int idx = blockIdx.x * 256 + threadIdx.x;
    const int stride = gridDim.x * 256;
    for (; idx < total; idx += stride) {
        const int m = idx >> 8;
        const int kq = (idx & 255) << 2;
        float4 xr = ((const float4*)Xr)[idx];
        float4 xi = ((const float4*)Xi)[idx];
        __nv_bfloat16 rh[4], rl[4], ih[4], il[4];
        split1(xr.x, rh[0], rl[0]); split1(xr.y, rh[1], rl[1]);
        split1(xr.z, rh[2], rl[2]); split1(xr.w, rh[3], rl[3]);
        split1(xi.x, ih[0], il[0]); split1(xi.y, ih[1], il[1]);
        split1(xi.z, ih[2], il[2]); split1(xi.w, ih[3], il[3]);
        __nv_bfloat16* base = A + (size_t)m * KE + kq;
        store4(base + 0,    rh[0], rh[1], rh[2], rh[3]);
        store4(base + 1024, rh[0], rh[1], rh[2], rh[3]);
        store4(base + 2048, rl[0], rl[1], rl[2], rl[3]);
        store4(base + 3072, ih[0], ih[1], ih[2], ih[3]);
        store4(base + 4096, ih[0], ih[1], ih[2], ih[3]);
        store4(base + 5120, il[0], il[1], il[2], il[3]);
    }
}

__global__ __launch_bounds__(256) void splitW_kernel(
    const float* __restrict__ Wr, const float* __restrict__ Wi,
    __nv_bfloat16* __restrict__ B1, __nv_bfloat16* __restrict__ B2)
{
    const int total = Esz * Esz / 4;
    int idx = blockIdx.x * 256 + threadIdx.x;
    const int stride = gridDim.x * 256;
    for (; idx < total; idx += stride) {
        const int n = idx >> 8;
        const int kq = (idx & 255) << 2;
        float4 wr = ((const float4*)Wr)[idx];
        float4 wi = ((const float4*)Wi)[idx];
        __nv_bfloat16 rh[4], rl[4], ih[4], il[4], nh[4], nl[4];
        split1(wr.x, rh[0], rl[0]); split1(wr.y, rh[1], rl[1]);
        split1(wr.z, rh[2], rl[2]); split1(wr.w, rh[3], rl[3]);
        split1(wi.x, ih[0], il[0]); split1(wi.y, ih[1], il[1]);
        split1(wi.z, ih[2], il[2]); split1(wi.w, ih[3], il[3]);
        split1(-wi.x, nh[0], nl[0]); split1(-wi.y, nh[1], nl[1]);
        split1(-wi.z, nh[2], nl[2]); split1(-wi.w, nh[3], nl[3]);
        __nv_bfloat16* b1 = B1 + (size_t)n * KE + kq;
        __nv_bfloat16* b2 = B2 + (size_t)n * KE + kq;
        store4(b1 + 0,    rh[0], rh[1], rh[2], rh[3]);
        store4(b1 + 1024, rl[0], rl[1], rl[2], rl[3]);
        store4(b1 + 2048, rh[0], rh[1], rh[2], rh[3]);
        store4(b1 + 3072, nh[0], nh[1], nh[2], nh[3]);
        store4(b1 + 4096, nl[0], nl[1], nl[2], nl[3]);
        store4(b1 + 5120, nh[0], nh[1], nh[2], nh[3]);
        store4(b2 + 0,    ih[0], ih[1], ih[2], ih[3]);
        store4(b2 + 1024, il[0], il[1], il[2], il[3]);
        store4(b2 + 2048, ih[0], ih[1], ih[2], ih[3]);
        store4(b2 + 3072, rh[0], rh[1], rh[2], rh[3]);
        store4(b2 + 4096, rl[0], rl[1], rl[2], rl[3]);
        store4(b2 + 5120, rh[0], rh[1], rh[2], rh[3]);
    }
}

// ---------------------------------------------------------------------------
// GEMM config: CTA 128x128, 512 threads (16 warps, warp 32x32), K-chunk 64,
// 3-stage cp.async, mma.sync bf16. Regs/thread forced <=128 -> 4 warps/SMSP.
// ---------------------------------------------------------------------------
#define GM 128
#define GN 128
#define KCH 64
#define NCHK (KE / KCH)                 // 96
#define ASTR 144
#define A_BYTES (GM * ASTR)
#define B_BYTES (GN * ASTR)
#define STAGE (A_BYTES + 2 * B_BYTES)   // 55296
#define GEMM_SMEM (3 * STAGE)           // 165888
#define GTHR 512

struct QKVBatch {
    const __nv_bfloat16* A[3];
    const __nv_bfloat16* B1[3];
    const __nv_bfloat16* B2[3];
    const float* br[3];
    const float* bi[3];
    __nv_bfloat16* RH[3];
    __nv_bfloat16* RL[3];
    __nv_bfloat16* IH[3];
    __nv_bfloat16* IL[3];
};

__device__ __forceinline__ void gemm_mainloop512(
    uint32_t sb, int tid, int m0, int n0,
    const __nv_bfloat16* A, const __nv_bfloat16* B1, const __nv_bfloat16* B2,
    float acc[2][2][4][4])
{
    const int lane = tid & 31;
    const int wid = tid >> 5;        // 0..15
    const int wm = wid >> 2;         // 0..3 (32 rows each)
    const int wn = wid & 3;          // 0..3 (32 cols each)

    auto load_chunk = [&](int c, int buf) {
        const uint32_t s = sb + buf * STAGE;
        const int kc = c * KCH;
        #pragma unroll
        for (int i = 0; i < 2; ++i) {
            const int op = tid + i * GTHR;
            const int r = op >> 3, q = op & 7;
            cpa16(s + r * ASTR + q * 16, A + (size_t)(m0 + r) * KE + kc + q * 8);
        }
        #pragma unroll
        for (int i = 0; i < 2; ++i) {
            const int op = tid + i * GTHR;
            const int r = op >> 3, q = op & 7;
            cpa16(s + A_BYTES + r * ASTR + q * 16,
                  B1 + (size_t)(n0 + r) * KE + kc + q * 8);
            cpa16(s + A_BYTES + B_BYTES + r * ASTR + q * 16,
                  B2 + (size_t)(n0 + r) * KE + kc + q * 8);
        }
        CPA_COMMIT();
    };

    const uint32_t aRowOff = (uint32_t)(wm * 32 + (lane & 15));
    const uint32_t aColB   = (uint32_t)((lane >> 4) * 16);
    const uint32_t bRowOff = (uint32_t)(wn * 32 + (lane & 7) + ((lane >> 4) << 3));
    const uint32_t bColB   = (uint32_t)(((lane >> 3) & 1) * 16);

    load_chunk(0, 0);
    load_chunk(1, 1);

    int buf = 0;
    for (int c = 0; c < NCHK; ++c) {
        if (c + 2 < NCHK) { load_chunk(c + 2, (buf + 2) % 3); CPA_WAIT(2); }
        else if (c + 1 < NCHK) CPA_WAIT(1);
        else CPA_WAIT(0);
        __syncthreads();

        const uint32_t s = sb + buf * STAGE;
        const uint32_t aB = s + aRowOff * ASTR + aColB;
        const uint32_t bB = s + A_BYTES + bRowOff * ASTR + bColB;

        #pragma unroll
        for (int ks = 0; ks < 4; ++ks) {
            uint32_t a[2][4];
            #pragma unroll
            for (int mt = 0; mt < 2; ++mt)
                ldsm_x4(a[mt], aB + mt * 16 * ASTR + ks * 32);
            uint32_t bf[2][2][4];
            #pragma unroll
            for (int o = 0; o < 2; ++o)
                #pragma unroll
                for (int np = 0; np < 2; ++np)
                    ldsm_x4(bf[o][np], bB + o * B_BYTES + np * 16 * ASTR + ks * 32);
            #pragma unroll
            for (int o = 0; o < 2; ++o)
                #pragma unroll
                for (int mt = 0; mt < 2; ++mt)
                    #pragma unroll
                    for (int nt = 0; nt < 4; ++nt)
                        mma16816(acc[o][mt][nt], a[mt], &bf[o][nt >> 1][(nt & 1) * 2]);
        }
        __syncthreads();
        buf = (buf + 1) % 3;
    }
}

// q/k/v batched GEMM: epilogue writes bf16 hi/lo [BH][L][D] (fp16 for V, z==2)
__global__ __launch_bounds__(GTHR, 1) void gemm_qkv_kernel(QKVBatch p)
{
    extern __shared__ char smem[];
    const uint32_t sb = smem_u32(smem);
    const int tid = threadIdx.x;
    const int lane = tid & 31;
    const int wid = tid >> 5;
    const int wm = wid >> 2;
    const int wn = wid & 3;
    const int m0 = blockIdx.y * GM;
    const int n0 = blockIdx.x * GN;
    const int z = blockIdx.z;

    float acc[2][2][4][4] = {};
    gemm_mainloop512(sb, tid, m0, n0, p.A[z], p.B1[z], p.B2[z], acc);

    const float* br = p.br[z];
    const float* bi = p.bi[z];
    __nv_bfloat16* RH = p.RH[z];
    __nv_bfloat16* RL = p.RL[z];
    __nv_bfloat16* IH = p.IH[z];
    __nv_bfloat16* IL = p.IL[z];

    const int rowb = m0 + wm * 32 + (lane >> 2);
    const int colb = n0 + wn * 32 + (lane & 3) * 2;
    #pragma unroll
    for (int mt = 0; mt < 2; ++mt) {
        #pragma unroll
        for (int nt = 0; nt < 4; ++nt) {
            const int col = colb + nt * 8;
            const float br0 = __ldg(&br[col]), br1 = __ldg(&br[col + 1]);
            const float bi0 = __ldg(&bi[col]), bi1 = __ldg(&bi[col + 1]);
            const int h = col >> 6, d = col & 63;
            #pragma unroll
            for (int hf = 0; hf < 2; ++hf) {
                const int row = rowb + mt * 16 + hf * 8;
                const int f = hf * 2;
                const int b = row >> 11, l = row & 2047;
                const size_t o = (((size_t)(b * Hsz + h) * Lsz) + l) * Dsz + d;
                float yr0 = acc[0][mt][nt][f]   + br0;
                float yr1 = acc[0][mt][nt][f+1] + br1;
                float yi0 = acc[1][mt][nt][f]   + bi0;
                float yi1 = acc[1][mt][nt][f+1] + bi1;
                if (z == 2) {
                    // V in fp16 hi/lo
                    __half h0 = __float2half(yr0), h1 = __float2half(yr1);
                    float r0 = yr0 - __half2float(h0), r1 = yr1 - __half2float(h1);
                    *(uint32_t*)&RH[o] = packh2(yr0, yr1);
                    *(uint32_t*)&RL[o] = packh2(r0, r1);
                    h0 = __float2half(yi0); h1 = __float2half(yi1);
                    r0 = yi0 - __half2float(h0); r1 = yi1 - __half2float(h1);
                    *(uint32_t*)&IH[o] = packh2(yi0, yi1);
                    *(uint32_t*)&IL[o] = packh2(r0, r1);
                } else {
                    __nv_bfloat16 h0, l0, h1, l1;
                    split1(yr0, h0, l0); split1(yr1, h1, l1);
                    *(uint32_t*)&RH[o] = packbf2(h0, h1);
                    *(uint32_t*)&RL[o] = packbf2(l0, l1);
                    split1(yi0, h0, l0); split1(yi1, h1, l1);
                    *(uint32_t*)&IH[o] = packbf2(h0, h1);
                    *(uint32_t*)&IL[o] = packbf2(l0, l1);
                }
            }
        }
    }
}

// output-layer GEMM: fp32 epilogue to [B,L,E]
__global__ __launch_bounds__(GTHR, 1) void gemm_kernel(
    const __nv_bfloat16* __restrict__ A,
    const __nv_bfloat16* __restrict__ B1,
    const __nv_bfloat16* __restrict__ B2,
    const float* __restrict__ br, const float* __restrict__ bi,
    float* __restrict__ Yr, float* __restrict__ Yi)
{
    extern __shared__ char smem[];
    const uint32_t sb = smem_u32(smem);
    const int tid = threadIdx.x;
    const int lane = tid & 31;
    const int wid = tid >> 5;
    const int wm = wid >> 2;
    const int wn = wid & 3;
    const int m0 = blockIdx.y * GM;
    const int n0 = blockIdx.x * GN;

    float acc[2][2][4][4] = {};
    gemm_mainloop512(sb, tid, m0, n0, A, B1, B2, acc);

    const int rowb = m0 + wm * 32 + (lane >> 2);
    const int colb = n0 + wn * 32 + (lane & 3) * 2;
    #pragma unroll
    for (int mt = 0; mt < 2; ++mt) {
        #pragma unroll
        for (int nt = 0; nt < 4; ++nt) {
            const int col = colb + nt * 8;
            const int row = rowb + mt * 16;
            const float br0 = __ldg(&br[col]), br1 = __ldg(&br[col + 1]);
            const float bi0 = __ldg(&bi[col]), bi1 = __ldg(&bi[col + 1]);
            float2 v;
            v.x = acc[0][mt][nt][0] + br0; v.y = acc[0][mt][nt][1] + br1;
            *(float2*)&Yr[(size_t)row * Esz + col] = v;
            v.x = acc[0][mt][nt][2] + br0; v.y = acc[0][mt][nt][3] + br1;
            *(float2*)&Yr[(size_t)(row + 8) * Esz + col] = v;
            v.x = acc[1][mt][nt][0] + bi0; v.y = acc[1][mt][nt][1] + bi1;
            *(float2*)&Yi[(size_t)row * Esz + col] = v;
            v.x = acc[1][mt][nt][2] + bi0; v.y = acc[1][mt][nt][3] + bi1;
            *(float2*)&Yi[(size_t)(row + 8) * Esz + col] = v;
        }
    }
}

// ---------------------------------------------------------------------------
// Tensor-core flash attention. Q/K bf16 hi/lo (6 score chains), P single fp16,
// V fp16 hi/lo (4 PV chains). Epilogue writes o-layer A_cat directly.
// ---------------------------------------------------------------------------
#define AT_STR 144
#define AT_MAT (64 * AT_STR)
#define AT_QMAT (128 * AT_STR)
#define AT_QBYTES (4 * AT_QMAT)
#define AT_STAGE (8 * AT_MAT)
#define AT_SMEM (AT_QBYTES + 2 * AT_STAGE)
#define NKT (Lsz / 64)

__global__ __launch_bounds__(256, 1) void attn_tc_kernel(
    const __nv_bfloat16* __restrict__ QRH, const __nv_bfloat16* __restrict__ QRL,
    const __nv_bfloat16* __restrict__ QIH, const __nv_bfloat16* __restrict__ QIL,
    const __nv_bfloat16* __restrict__ KRH, const __nv_bfloat16* __restrict__ KRL,
    const __nv_bfloat16* __restrict__ KIH, const __nv_bfloat16* __restrict__ KIL,
    const __half* __restrict__ VRH, const __half* __restrict__ VRL,
    const __half* __restrict__ VIH, const __half* __restrict__ VIL,
    __nv_bfloat16* __restrict__ Ao)
{
    extern __shared__ char smem[];
    const uint32_t sb = smem_u32(smem);
    const int tid = threadIdx.x;
    const int lane = tid & 31;
    const int wid = tid >> 5;
    const int q0 = blockIdx.x * 128;
    const int bh = blockIdx.y;
    const size_t pb = (size_t)bh * Lsz * Dsz;

    const __nv_bfloat16* Qm[4] = {QRH + pb, QRL + pb, QIH + pb, QIL + pb};
    const void* Km[8] = {KRH + pb, KRL + pb, KIH + pb, KIL + pb,
                         VRH + pb, VRL + pb, VIH + pb, VIL + pb};

    #pragma unroll
    for (int mat = 0; mat < 4; ++mat) {
        #pragma unroll
        for (int i = 0; i < 4; ++i) {
            const int op = tid + i * 256;
            const int r = op >> 3, q = op & 7;
            cpa16(sb + mat * AT_QMAT + r * AT_STR + q * 16,
                  Qm[mat] + (size_t)(q0 + r) * Dsz + q * 8);
        }
    }
    CPA_COMMIT();

    auto issue_kv = [&](int kt, int buf) {
        const uint32_t base = sb + AT_QBYTES + buf * AT_STAGE;
        #pragma unroll
        for (int mat = 0; mat < 8; ++mat) {
            #pragma unroll
            for (int i = 0; i < 2; ++i) {
                const int op = tid + i * 256;
                const int r = op >> 3, q = op & 7;
                cpa16(base + mat * AT_MAT + r * AT_STR + q * 16,
                      (const char*)Km[mat] + ((size_t)(kt * 64 + r) * Dsz + q * 8) * 2);
            }
        }
        CPA_COMMIT();
    };

    issue_kv(0, 0);
    CPA_WAIT(0);
    __syncthreads();

    float oR[8][4] = {};
    float oI[8][4] = {};
    float mrun0 = -INFINITY, mrun1 = -INFINITY;
    float lrun0 = 0.f, lrun1 = 0.f;
    const float sc = 0.125f * 1.4426950408889634f;

    const uint32_t aoff = (uint32_t)((wid * 16 + (lane & 15)) * AT_STR + (lane >> 4) * 16);
    const uint32_t boff = (uint32_t)(((lane & 7) + ((lane >> 4) << 3)) * AT_STR
                                     + ((lane >> 3) & 1) * 16);
    const uint32_t voff = (uint32_t)((lane & 15) * AT_STR + (lane >> 4) * 16);

    for (int kt = 0; kt < NKT; ++kt) {
        if (kt + 1 < NKT) { issue_kv(kt + 1, (kt + 1) & 1); CPA_WAIT(1); }
        else CPA_WAIT(0);
        __syncthreads();
        const uint32_t kb = sb + AT_QBYTES + (kt & 1) * AT_STAGE;

        // ---- scores: 6 bf16 hi/lo chains, fragments loaded once ----
        float sacc[8][4] = {};
        #pragma unroll
        for (int ks = 0; ks < 4; ++ks) {
            uint32_t aq[4][4];
            #pragma unroll
            for (int m = 0; m < 4; ++m)
                ldsm_x4(aq[m], sb + m * AT_QMAT + aoff + ks * 32);
            #pragma unroll
            for (int np = 0; np < 4; ++np) {
                uint32_t kf[4][4];
                #pragma unroll
                for (int m = 0; m < 4; ++m)
                    ldsm_x4(kf[m], kb + m * AT_MAT + boff + np * 16 * AT_STR + ks * 32);
                mma16816(sacc[2*np],   aq[0], &kf[0][0]);
                mma16816(sacc[2*np+1], aq[0], &kf[0][2]);
                mma16816(sacc[2*np],   aq[0], &kf[1][0]);
                mma16816(sacc[2*np+1], aq[0], &kf[1][2]);
                mma16816(sacc[2*np],   aq[1], &kf[0][0]);
                mma16816(sacc[2*np+1], aq[1], &kf[0][2]);
                mma16816(sacc[2*np],   aq[2], &kf[2][0]);
                mma16816(sacc[2*np+1], aq[2], &kf[2][2]);
                mma16816(sacc[2*np],   aq[2], &kf[3][0]);
                mma16816(sacc[2*np+1], aq[2], &kf[3][2]);
                mma16816(sacc[2*np],   aq[3], &kf[2][0]);
                mma16816(sacc[2*np+1], aq[3], &kf[2][2]);
            }
        }

        // ---- online softmax, P -> single fp16 digit ----
        float mt0 = -INFINITY, mt1 = -INFINITY;
        #pragma unroll
        for (int j = 0; j < 8; ++j) {
            mt0 = fmaxf(mt0, fmaxf(sacc[j][0], sacc[j][1]));
            mt1 = fmaxf(mt1, fmaxf(sacc[j][2], sacc[j][3]));
        }
        mt0 = fmaxf(mt0, __shfl_xor_sync(0xffffffffu, mt0, 1));
        mt0 = fmaxf(mt0, __shfl_xor_sync(0xffffffffu, mt0, 2));
        mt1 = fmaxf(mt1, __shfl_xor_sync(0xffffffffu, mt1, 1));
        mt1 = fmaxf(mt1, __shfl_xor_sync(0xffffffffu, mt1, 2));
        const float mn0 = fmaxf(mrun0, mt0 * sc);
        const float mn1 = fmaxf(mrun1, mt1 * sc);

        float rs0 = 0.f, rs1 = 0.f;
        uint32_t ph[4][4];
        #pragma unroll
        for (int j = 0; j < 8; ++j) {
            float p0 = fexp2(fmaf(sacc[j][0], sc, -mn0));
            float p1 = fexp2(fmaf(sacc[j][1], sc, -mn0));
            float p2 = fexp2(fmaf(sacc[j][2], sc, -mn1));
            float p3 = fexp2(fmaf(sacc[j][3], sc, -mn1));
            rs0 += p0 + p1;
            rs1 += p2 + p3;
            const int ks = j >> 1;
            const int hx = (j & 1) * 2;
            ph[ks][hx + 0] = packh2(p0, p1);
            ph[ks][hx + 1] = packh2(p2, p3);
        }

        rs0 += __shfl_xor_sync(0xffffffffu, rs0, 1);
        rs0 += __shfl_xor_sync(0xffffffffu, rs0, 2);
        rs1 += __shfl_xor_sync(0xffffffffu, rs1, 1);
        rs1 += __shfl_xor_sync(0xffffffffu, rs1, 2);
        const float c0 = fexp2(mrun0 - mn0);
        const float c1 = fexp2(mrun1 - mn1);
        lrun0 = lrun0 * c0 + rs0;
        lrun1 = lrun1 * c1 + rs1;
        mrun0 = mn0; mrun1 = mn1;
        #pragma unroll
        for (int j = 0; j < 8; ++j) {
            oR[j][0] *= c0; oR[j][1] *= c0; oR[j][2] *= c1; oR[j][3] *= c1;
            oI[j][0] *= c0; oI[j][1] *= c0; oI[j][2] *= c1; oI[j][3] *= c1;
        }

        // ---- O += P @ V : 4 fp16 chains ----
        #pragma unroll
        for (int ks = 0; ks < 4; ++ks) {
            #pragma unroll
            for (int np = 0; np < 4; ++np) {
                uint32_t vf[4][4];
                #pragma unroll
                for (int m = 0; m < 4; ++m)
                    ldsm_x4_t(vf[m], kb + (4 + m) * AT_MAT + voff
                                       + ks * 16 * AT_STR + np * 32);
                mma16816h(oR[2*np],   ph[ks], &vf[0][0]);
                mma16816h(oR[2*np+1], ph[ks], &vf[0][2]);
                mma16816h(oR[2*np],   ph[ks], &vf[1][0]);
                mma16816h(oR[2*np+1], ph[ks], &vf[1][2]);
                mma16816h(oI[2*np],   ph[ks], &vf[2][0]);
                mma16816h(oI[2*np+1], ph[ks], &vf[2][2]);
                mma16816h(oI[2*np],   ph[ks], &vf[3][0]);
                mma16816h(oI[2*np+1], ph[ks], &vf[3][2]);
            }
        }
        __syncthreads();
    }

    // ---- finalize: write o-layer A_cat (bf16 hi/lo, 6 blocks) directly ----
    const float inv0 = 1.0f / lrun0;
    const float inv1 = 1.0f / lrun1;
    const int b = bh >> 4, h = bh & 15;
    const int row0 = q0 + wid * 16 + (lane >> 2);
    #pragma unroll
    for (int j = 0; j < 8; ++j) {
        const int e = h * 64 + j * 8 + (lane & 3) * 2;
        #pragma unroll
        for (int hf = 0; hf < 2; ++hf) {
            const int l = row0 + hf * 8;
            const float inv = (hf == 0) ? inv0 : inv1;
            const int f = hf * 2;
            const float yr0 = oR[j][f] * inv,  yr1 = oR[j][f+1] * inv;
            const float yi0 = oI[j][f] * inv,  yi1 = oI[j][f+1] * inv;
            __nv_bfloat16* base = Ao + (size_t)(b * Lsz + l) * KE + e;
            __nv_bfloat16 h0, l0, h1, l1;
            split1(yr0, h0, l0); split1(yr1, h1, l1);
            const uint32_t rhi = packbf2(h0, h1), rlo = packbf2(l0, l1);
            split1(yi0, h0, l0); split1(yi1, h1, l1);
            const uint32_t ihi = packbf2(h0, h1), ilo = packbf2(l0, l1);
            *(uint32_t*)(base + 0)    = rhi;
            *(uint32_t*)(base + 1024) = rhi;
            *(uint32_t*)(base + 2048) = rlo;
            *(uint32_t*)(base + 3072) = ihi;
            *(uint32_t*)(base + 4096) = ihi;
            *(uint32_t*)(base + 5120) = ilo;
        }
    }
}

// ---------------------------------------------------------------------------
extern "C" void kernel_launch(void* const* d_in, const int* in_sizes, int n_in,
                              void* d_out, int out_size)
{
    (void)in_sizes; (void)n_in; (void)out_size;
    const float* query_r = (const float*)d_in[0];
    const float* query_i = (const float*)d_in[1];
    const float* key_r   = (const float*)d_in[2];
    const float* key_i   = (const float*)d_in[3];
    const float* value_r = (const float*)d_in[4];
    const float* value_i = (const float*)d_in[5];
    const float* Wq_r = (const float*)d_in[6];
    const float* Wq_i = (const float*)d_in[7];
    const float* bq_r = (const float*)d_in[8];
    const float* bq_i = (const float*)d_in[9];
    const float* Wk_r = (const float*)d_in[10];
    const float* Wk_i = (const float*)d_in[11];
    const float* bk_r = (const float*)d_in[12];
    const float* bk_i = (const float*)d_in[13];
    const float* Wv_r = (const float*)d_in[14];
    const float* Wv_i = (const float*)d_in[15];
    const float* bv_r = (const float*)d_in[16];
    const float* bv_i = (const float*)d_in[17];
    const float* Wo_r = (const float*)d_in[18];
    const float* Wo_i = (const float*)d_in[19];
    const float* bo_r = (const float*)d_in[20];
    const float* bo_i = (const float*)d_in[21];

    __nv_bfloat16* acat = nullptr;
    cudaGetSymbolAddress((void**)&acat, g_acat);
    __nv_bfloat16* bcat = nullptr;
    cudaGetSymbolAddress((void**)&bcat, g_bcat);
    __nv_bfloat16* attn = nullptr;
    cudaGetSymbolAddress((void**)&attn, g_attn);

    auto Wc = [&](int s) { return bcat + (size_t)s * Esz * KE; };
    auto Ac = [&](int s) { return acat + (size_t)s * NROW * KE; };
    auto At = [&](int s) { return attn + (size_t)s * BHD; };

    splitW_kernel<<<512, 256>>>(Wq_r, Wq_i, Wc(0), Wc(1));
    splitW_kernel<<<512, 256>>>(Wk_r, Wk_i, Wc(2), Wc(3));
    splitW_kernel<<<512, 256>>>(Wv_r, Wv_i, Wc(4), Wc(5));
    splitW_kernel<<<512, 256>>>(Wo_r, Wo_i, Wc(6), Wc(7));

    splitA_kernel<<<1024, 256>>>(query_r, query_i, Ac(0));
    splitA_kernel<<<1024, 256>>>(key_r,   key_i,   Ac(1));
    splitA_kernel<<<1024, 256>>>(value_r, value_i, Ac(2));

    QKVBatch batch;
    batch.A[0] = Ac(0); batch.A[1] = Ac(1); batch.A[2] = Ac(2);
    batch.B1[0] = Wc(0); batch.B2[0] = Wc(1);
    batch.B1[1] = Wc(2); batch.B2[1] = Wc(3);
    batch.B1[2] = Wc(4); batch.B2[2] = Wc(5);
    batch.br[0] = bq_r; batch.bi[0] = bq_i;
    batch.br[1] = bk_r; batch.bi[1] = bk_i;
    batch.br[2] = bv_r; batch.bi[2] = bv_i;
    for (int z = 0; z < 3; ++z) {
        batch.RH[z] = At(4 * z + 0);
        batch.RL[z] = At(4 * z + 1);
        batch.IH[z] = At(4 * z + 2);
        batch.IL[z] = At(4 * z + 3);
    }

    cudaFuncSetAttribute((const void*)gemm_qkv_kernel,
                         cudaFuncAttributeMaxDynamicSharedMemorySize, GEMM_SMEM);
    cudaFuncSetAttribute((const void*)gemm_kernel,
                         cudaFuncAttributeMaxDynamicSharedMemorySize, GEMM_SMEM);

    gemm_qkv_kernel<<<dim3(Esz / GN, NROW / GM, 3), GTHR, GEMM_SMEM>>>(batch);

    cudaFuncSetAttribute((const void*)attn_tc_kernel,
                         cudaFuncAttributeMaxDynamicSharedMemorySize, AT_SMEM);
    attn_tc_kernel<<<dim3(Lsz / 128, Bsz * Hsz), 256, AT_SMEM>>>(
        At(0), At(1), At(2), At(3), At(4), At(5), At(6), At(7),
        (const __half*)At(8), (const __half*)At(9),
        (const __half*)At(10), (const __half*)At(11), Ac(0));

    float* yr = (float*)d_out;
    float* yi = yr + BLE;
    gemm_kernel<<<dim3(Esz / GN, NROW / GM), GTHR, GEMM_SMEM>>>(
        Ac(0), Wc(6), Wc(7), bo_r, bo_i, yr, yi);
}